// round 12
// baseline (speedup 1.0000x reference)
#include <cuda_runtime.h>
#include <cuda_bf16.h>
#include <math.h>
#include <stdint.h>

#define NN 100000
#define EE 1600000
#define DD 64
#define EDIM 16
#define SHC 9
#define FEAT 25
#define TE 128            // edges per tile
#define NT (EE / TE)      // 12500
#define SCAN_B 98         // ceil(NN/1024)

typedef unsigned long long u64;

// ---------------- scratch (device globals) ----------------------------------
__device__ float  g_xt[(size_t)NN * DD];
__device__ float  g_s [(size_t)NN * DD];
__device__ int    g_cnti[NN];
__device__ int    g_cur[NN];
__device__ int    g_bsum[128];
__device__ int    g_eidx[EE];
__device__ int    g_srow[EE];
__device__ int    g_scol[EE];
__device__ float  g_h [(size_t)NN * DD];
__device__ double g_sum[DD];
__device__ double g_sumsq[DD];

__device__ __forceinline__ float silu_f(float a) {
    return a / (1.0f + __expf(-a));
}
__device__ __forceinline__ u64 pk2(float x, float y) {
    u64 r; asm("mov.b64 %0, {%1,%2};" : "=l"(r) : "f"(x), "f"(y)); return r;
}
__device__ __forceinline__ void upk2(u64 v, float& x, float& y) {
    asm("mov.b64 {%0,%1}, %2;" : "=f"(x), "=f"(y) : "l"(v));
}
__device__ __forceinline__ void fma2(u64& d, u64 a, u64 b) {
    asm("fma.rn.f32x2 %0, %1, %2, %0;" : "+l"(d) : "l"(a), "l"(b));
}
__device__ __forceinline__ void red_add_v2(float* p, float a, float b) {
    asm volatile("red.global.add.v2.f32 [%0], {%1,%2};"
                 :: "l"(p), "f"(a), "f"(b) : "memory");
}
__device__ __forceinline__ uint32_t s2u(const void* p) {
    uint32_t a;
    asm("{ .reg .u64 t; cvta.to.shared.u64 t, %1; cvt.u32.u64 %0, t; }" : "=r"(a) : "l"(p));
    return a;
}

// ---------------- mma.sync / ldmatrix primitives -----------------------------
__device__ __forceinline__ void ldsm4(uint32_t* r, uint32_t a) {
    asm volatile("ldmatrix.sync.aligned.m8n8.x4.shared.b16 {%0,%1,%2,%3}, [%4];"
                 : "=r"(r[0]), "=r"(r[1]), "=r"(r[2]), "=r"(r[3]) : "r"(a));
}
__device__ __forceinline__ void ldsm4t(uint32_t* r, uint32_t a) {
    asm volatile("ldmatrix.sync.aligned.m8n8.x4.trans.shared.b16 {%0,%1,%2,%3}, [%4];"
                 : "=r"(r[0]), "=r"(r[1]), "=r"(r[2]), "=r"(r[3]) : "r"(a));
}
__device__ __forceinline__ void mma16816(float* c, const uint32_t* a,
                                         uint32_t b0, uint32_t b1) {
    asm volatile(
        "mma.sync.aligned.m16n8k16.row.col.f32.bf16.bf16.f32 "
        "{%0,%1,%2,%3}, {%4,%5,%6,%7}, {%8,%9}, {%0,%1,%2,%3};"
        : "+f"(c[0]), "+f"(c[1]), "+f"(c[2]), "+f"(c[3])
        : "r"(a[0]), "r"(a[1]), "r"(a[2]), "r"(a[3]), "r"(b0), "r"(b1));
}

__device__ __forceinline__ void split8(const float* v, uint4& hi, uint4& lo) {
    uint32_t h[4], l[4];
    #pragma unroll
    for (int p = 0; p < 4; p++) {
        float a = v[2*p], b = v[2*p+1];
        __nv_bfloat162 hh = __floats2bfloat162_rn(a, b);
        float la = a - __bfloat162float(__low2bfloat16(hh));
        float lb = b - __bfloat162float(__high2bfloat16(hh));
        __nv_bfloat162 ll = __floats2bfloat162_rn(la, lb);
        h[p] = *(uint32_t*)&hh; l[p] = *(uint32_t*)&ll;
    }
    hi = make_uint4(h[0], h[1], h[2], h[3]);
    lo = make_uint4(l[0], l[1], l[2], l[3]);
}
__device__ __forceinline__ void split2(float a, float b, uint32_t& hi, uint32_t& lo) {
    __nv_bfloat162 hh = __floats2bfloat162_rn(a, b);
    float la = a - __bfloat162float(__low2bfloat16(hh));
    float lb = b - __bfloat162float(__high2bfloat16(hh));
    __nv_bfloat162 ll = __floats2bfloat162_rn(la, lb);
    hi = *(uint32_t*)&hh; lo = *(uint32_t*)&ll;
}

// ---------------- zero + counting-sort kernels --------------------------------
__global__ void zero_kernel() {
    int idx = blockIdx.x * blockDim.x + threadIdx.x;
    int stride = gridDim.x * blockDim.x;
    float4 z = make_float4(0.f, 0.f, 0.f, 0.f);
    for (int i = idx; i < NN * (DD / 4); i += stride)
        ((float4*)g_s)[i] = z;
    for (int i = idx; i < NN; i += stride)
        g_cnti[i] = 0;
    if (idx < DD) { g_sum[idx] = 0.0; g_sumsq[idx] = 0.0; }
}

__global__ void count_kernel(const int* __restrict__ col) {
    int idx = blockIdx.x * blockDim.x + threadIdx.x;
    int stride = gridDim.x * blockDim.x;
    for (int e = idx; e < EE; e += stride)
        atomicAdd(&g_cnti[col[e]], 1);
}

__global__ void scan1_kernel() {           // per-block exclusive scan (1024)
    __shared__ int sh[1024];
    int t = threadIdx.x;
    int i = blockIdx.x * 1024 + t;
    int v = (i < NN) ? g_cnti[i] : 0;
    sh[t] = v;
    __syncthreads();
    for (int d = 1; d < 1024; d <<= 1) {
        int u = (t >= d) ? sh[t - d] : 0;
        __syncthreads();
        sh[t] += u;
        __syncthreads();
    }
    if (i < NN) g_cur[i] = sh[t] - v;      // block-local exclusive
    if (t == 1023) g_bsum[blockIdx.x] = sh[t];
}

__global__ void scan2_kernel() {           // scan of block sums (single block)
    __shared__ int sh[128];
    int t = threadIdx.x;
    int v = (t < SCAN_B) ? g_bsum[t] : 0;
    sh[t] = v;
    __syncthreads();
    for (int d = 1; d < 128; d <<= 1) {
        int u = (t >= d) ? sh[t - d] : 0;
        __syncthreads();
        sh[t] += u;
        __syncthreads();
    }
    if (t < SCAN_B) g_bsum[t] = sh[t] - v; // exclusive
}

__global__ void scan3_kernel() {
    int i = blockIdx.x * 1024 + threadIdx.x;
    if (i < NN) g_cur[i] += g_bsum[i >> 10];
}

__global__ void permute_kernel(const int* __restrict__ row,
                               const int* __restrict__ col) {
    int idx = blockIdx.x * blockDim.x + threadIdx.x;
    int stride = gridDim.x * blockDim.x;
    for (int e = idx; e < EE; e += stride) {
        int c = col[e];
        int p = atomicAdd(&g_cur[c], 1);
        g_eidx[p] = e;
        g_srow[p] = row[e];
        g_scol[p] = c;
    }
}

// ---------------- node / output MLP (R5, unchanged) --------------------------
template <bool IS_OUT>
__global__ __launch_bounds__(128)
void mlp_kernel(const float* __restrict__ x,
                const float* __restrict__ W1, const float* __restrict__ b1,
                const float* __restrict__ W2, const float* __restrict__ b2)
{
    constexpr int IND = IS_OUT ? 128 : 64;
    __shared__ __align__(16) float sW1[IND * DD];
    __shared__ __align__(16) float sW2[DD * DD];
    const int t = threadIdx.x;
    for (int i = t; i < IND * DD; i += 128) sW1[i] = W1[i];
    for (int i = t; i < DD * DD;  i += 128) sW2[i] = W2[i];
    __syncthreads();

    const int id = blockIdx.x * 128 + t;
    const bool valid = (id < NN);
    const int rid = valid ? id : (NN - 1);

    const float4* rowA;
    const float4* rowB = nullptr;
    if (IS_OUT) {
        rowA = (const float4*)(g_s + (size_t)rid * DD);
        rowB = (const float4*)(x   + (size_t)rid * DD);
    } else {
        rowA = (const float4*)(x + (size_t)rid * DD);
    }

    u64 outp[32];
    {
        const ulonglong2* b2v = (const ulonglong2*)b2;
        #pragma unroll
        for (int q = 0; q < 16; q++) { ulonglong2 bv = b2v[q]; outp[2*q] = bv.x; outp[2*q+1] = bv.y; }
    }

    #pragma unroll 1
    for (int ch = 0; ch < 4; ch++) {
        const int base = ch * 16;
        u64 hp[8];
        {
            const ulonglong2* b1v = (const ulonglong2*)(b1 + base);
            #pragma unroll
            for (int q = 0; q < 4; q++) { ulonglong2 bv = b1v[q]; hp[2*q] = bv.x; hp[2*q+1] = bv.y; }
        }
        #pragma unroll 2
        for (int g = 0; g < IND / 4; g++) {
            float4 v;
            if (IS_OUT) v = (g < 16) ? rowA[g] : rowB[g - 16];
            else        v = rowA[g];
            const float fv[4] = {v.x, v.y, v.z, v.w};
            #pragma unroll
            for (int u = 0; u < 4; u++) {
                const u64 fmp = pk2(fv[u], fv[u]);
                const ulonglong2* wr = (const ulonglong2*)(sW1 + (g*4 + u) * DD + base);
                #pragma unroll
                for (int q = 0; q < 4; q++) {
                    ulonglong2 w = wr[q];
                    fma2(hp[2*q], fmp, w.x);
                    fma2(hp[2*q+1], fmp, w.y);
                }
            }
        }
        float h16[16];
        #pragma unroll
        for (int i = 0; i < 8; i++) {
            float a, b; upk2(hp[i], a, b);
            h16[2*i] = silu_f(a); h16[2*i+1] = silu_f(b);
        }
        #pragma unroll
        for (int kk = 0; kk < 16; kk++) {
            const u64 hvp = pk2(h16[kk], h16[kk]);
            const ulonglong2* wr = (const ulonglong2*)(sW2 + (base + kk) * DD);
            #pragma unroll
            for (int q = 0; q < 16; q++) {
                ulonglong2 w = wr[q];
                fma2(outp[2*q], hvp, w.x);
                fma2(outp[2*q+1], hvp, w.y);
            }
        }
    }

    float* dst = IS_OUT ? g_h : g_xt;
    if (valid) {
        ulonglong2* o = (ulonglong2*)(dst + (size_t)id * DD);
        #pragma unroll
        for (int q = 0; q < 16; q++) {
            ulonglong2 w; w.x = outp[2*q]; w.y = outp[2*q+1];
            o[q] = w;
        }
    }

    if (IS_OUT) {
        #pragma unroll
        for (int jp = 0; jp < 32; jp++) {
            float va, vb; upk2(outp[jp], va, vb);
            if (!valid) { va = 0.f; vb = 0.f; }
            float s0 = va, q0 = va * va, s1 = vb, q1 = vb * vb;
            #pragma unroll
            for (int o = 16; o; o >>= 1) {
                s0 += __shfl_down_sync(0xffffffffu, s0, o);
                q0 += __shfl_down_sync(0xffffffffu, q0, o);
                s1 += __shfl_down_sync(0xffffffffu, s1, o);
                q1 += __shfl_down_sync(0xffffffffu, q1, o);
            }
            if ((t & 31) == 0) {
                atomicAdd(&g_sum[2*jp],     (double)s0);
                atomicAdd(&g_sumsq[2*jp],   (double)q0);
                atomicAdd(&g_sum[2*jp+1],   (double)s1);
                atomicAdd(&g_sumsq[2*jp+1], (double)q1);
            }
        }
    }
}

// ---------------- fused edge kernel: col-sorted HMMA + segmented scatter -----
// Edges pre-sorted by col. After GEMM2, EW(+b2) staged feature-major in smem
// (sEW[feature][edge], stride 128 f32 -> conflict-free). Scatter: warp window
// of 32 sorted edges, __match_any on col, in-warp segmented reduce, leader-only
// red.add.v2 -> ~10x fewer atomic words.
#define SA1 80
#define SA2 144
#define SW  144
#define OFF_B2   0
#define OFF_ROW  256
#define OFF_COL  768
#define OFF_A1H  1280
#define OFF_A1L  11520
#define OFF_A2H  21760
#define OFF_A2L  40192
#define OFF_EW   21760       // overlays A2 (32768 <= 36864)
#define OFF_W1H  58624
#define OFF_W1L  63232
#define OFF_W2H  67840
#define OFF_W2L  77056
#define EDGE_SMEM 86272

__global__ __launch_bounds__(128, 2)
void edge_kernel(const float* __restrict__ pos,
                 const float* __restrict__ edge_attr,
                 const float* __restrict__ W1, const float* __restrict__ b1,
                 const float* __restrict__ W2, const float* __restrict__ b2)
{
    extern __shared__ __align__(16) char smem[];
    const uint32_t sb = s2u(smem);
    const int t    = threadIdx.x;
    const int wid  = t >> 5;
    const int lane = t & 31;
    const int m0   = wid * 32;

    float* sB2  = (float*)(smem + OFF_B2);
    int*   sRow = (int*)(smem + OFF_ROW);
    int*   sCol = (int*)(smem + OFF_COL);
    float* sEW  = (float*)(smem + OFF_EW);

    // ---- one-time: weights -> bf16 hi/lo, [k][n] row-major, stride SW ----
    for (int i = t; i < 32 * 64; i += 128) {
        int k = i >> 6, n = i & 63;
        float v = (k < FEAT) ? W1[k * 64 + n] : ((k == FEAT) ? b1[n] : 0.f);
        uint32_t o = (uint32_t)(k * SW + n * 2);
        __nv_bfloat16 h = __float2bfloat16(v);
        *(__nv_bfloat16*)(smem + OFF_W1H + o) = h;
        *(__nv_bfloat16*)(smem + OFF_W1L + o) = __float2bfloat16(v - __bfloat162float(h));
    }
    for (int i = t; i < 64 * 64; i += 128) {
        int k = i >> 6, n = i & 63;
        float v = W2[k * 64 + n];
        uint32_t o = (uint32_t)(k * SW + n * 2);
        __nv_bfloat16 h = __float2bfloat16(v);
        *(__nv_bfloat16*)(smem + OFF_W2H + o) = h;
        *(__nv_bfloat16*)(smem + OFF_W2L + o) = __float2bfloat16(v - __bfloat162float(h));
    }
    if (t < 64) sB2[t] = b2[t];
    __syncthreads();

    float2 b2p[8];
    {
        const int cb = 2 * (lane & 3);
        #pragma unroll
        for (int nf = 0; nf < 8; nf++)
            b2p[nf] = *(float2*)(sB2 + nf*8 + cb);
    }

    const uint32_t aA1H = sb + OFF_A1H, aA1L = sb + OFF_A1L;
    const uint32_t aA2H = sb + OFF_A2H, aA2L = sb + OFF_A2L;
    const uint32_t aW1H = sb + OFF_W1H, aW1L = sb + OFF_W1L;
    const uint32_t aW2H = sb + OFF_W2H, aW2L = sb + OFF_W2L;

    for (int tile = blockIdx.x; tile < NT; tile += gridDim.x) {
        const int p = tile * TE + t;

        // ---- phase 1: per-edge features (bf16 hi/lo) -> A1 row t ----
        {
            const int e = g_eidx[p];
            const int r = g_srow[p];
            const int c = g_scol[p];
            sRow[t] = r; sCol[t] = c;

            float px = pos[3*r]   - pos[3*c];
            float py = pos[3*r+1] - pos[3*c+1];
            float pz = pos[3*r+2] - pos[3*c+2];
            float len = sqrtf(px*px + py*py + pz*pz + 1e-12f);
            float dx = px / len, dy = py / len, dz = pz / len;
            float n2 = sqrtf(dx*dx + dy*dy + dz*dz) + 1e-10f;
            dx /= n2; dy /= n2; dz /= n2;

            float f[32];
            f[0] = 0.28209479177387814f;
            f[1] = 0.4886025119029199f * dy;
            f[2] = 0.4886025119029199f * dz;
            f[3] = 0.4886025119029199f * dx;
            f[4] = 1.0925484305920792f * dx * dy;
            f[5] = 1.0925484305920792f * dy * dz;
            f[6] = 0.31539156525252005f * (3.0f * dz * dz - 1.0f);
            f[7] = 1.0925484305920792f * dx * dz;
            f[8] = 0.5462742152960396f * (dx*dx - dy*dy);
            const float4* ea = (const float4*)(edge_attr + (size_t)e * EDIM);
            #pragma unroll
            for (int i = 0; i < 4; i++) {
                float4 v = ea[i];
                f[SHC + 4*i]   = v.x; f[SHC + 4*i+1] = v.y;
                f[SHC + 4*i+2] = v.z; f[SHC + 4*i+3] = v.w;
            }
            f[25] = 1.0f;
            #pragma unroll
            for (int k = 26; k < 32; k++) f[k] = 0.f;

            #pragma unroll
            for (int cc = 0; cc < 4; cc++) {
                uint4 hi, lo;
                split8(f + cc*8, hi, lo);
                *(uint4*)(smem + OFF_A1H + t*SA1 + cc*16) = hi;
                *(uint4*)(smem + OFF_A1L + t*SA1 + cc*16) = lo;
            }
        }
        __syncthreads();

        // ---- GEMM1: K=32, 3 passes ----
        float C[2][8][4];
        #pragma unroll
        for (int mf = 0; mf < 2; mf++)
            #pragma unroll
            for (int nf = 0; nf < 8; nf++)
                #pragma unroll
                for (int q = 0; q < 4; q++) C[mf][nf][q] = 0.f;

        #pragma unroll
        for (int pass = 0; pass < 3; pass++) {
            const uint32_t Ab = (pass == 2) ? aA1L : aA1H;
            const uint32_t Wb = (pass == 1) ? aW1L : aW1H;
            #pragma unroll
            for (int ks = 0; ks < 2; ks++) {
                uint32_t af[2][4];
                #pragma unroll
                for (int mf = 0; mf < 2; mf++)
                    ldsm4(af[mf], Ab + (uint32_t)((m0 + 16*mf + (lane & 15)) * SA1
                                                  + ks*32 + (lane >> 4) * 16));
                #pragma unroll
                for (int np = 0; np < 4; np++) {
                    uint32_t bf[4];
                    ldsm4t(bf, Wb + (uint32_t)((ks*16 + (lane & 7) + 8*((lane >> 3) & 1)) * SW
                                               + (np*16 + (lane >> 4) * 8) * 2));
                    #pragma unroll
                    for (int mf = 0; mf < 2; mf++) {
                        mma16816(C[mf][2*np],     af[mf], bf[0], bf[1]);
                        mma16816(C[mf][2*np + 1], af[mf], bf[2], bf[3]);
                    }
                }
            }
        }

        // ---- silu -> bf16 hi/lo -> A2 ----
        #pragma unroll
        for (int mf = 0; mf < 2; mf++) {
            const int r0 = m0 + 16*mf + (lane >> 2);
            #pragma unroll
            for (int nf = 0; nf < 8; nf++) {
                const int cb = (nf*8 + 2*(lane & 3)) * 2;
                uint32_t hi, lo;
                split2(silu_f(C[mf][nf][0]), silu_f(C[mf][nf][1]), hi, lo);
                *(uint32_t*)(smem + OFF_A2H + r0*SA2 + cb) = hi;
                *(uint32_t*)(smem + OFF_A2L + r0*SA2 + cb) = lo;
                split2(silu_f(C[mf][nf][2]), silu_f(C[mf][nf][3]), hi, lo);
                *(uint32_t*)(smem + OFF_A2H + (r0+8)*SA2 + cb) = hi;
                *(uint32_t*)(smem + OFF_A2L + (r0+8)*SA2 + cb) = lo;
            }
        }
        __syncthreads();

        // ---- GEMM2: K=64, 3 passes ----
        #pragma unroll
        for (int mf = 0; mf < 2; mf++)
            #pragma unroll
            for (int nf = 0; nf < 8; nf++)
                #pragma unroll
                for (int q = 0; q < 4; q++) C[mf][nf][q] = 0.f;

        #pragma unroll
        for (int pass = 0; pass < 3; pass++) {
            const uint32_t Ab = (pass == 2) ? aA2L : aA2H;
            const uint32_t Wb = (pass == 1) ? aW2L : aW2H;
            #pragma unroll
            for (int ks = 0; ks < 4; ks++) {
                uint32_t af[2][4];
                #pragma unroll
                for (int mf = 0; mf < 2; mf++)
                    ldsm4(af[mf], Ab + (uint32_t)((m0 + 16*mf + (lane & 15)) * SA2
                                                  + ks*32 + (lane >> 4) * 16));
                #pragma unroll
                for (int np = 0; np < 4; np++) {
                    uint32_t bf[4];
                    ldsm4t(bf, Wb + (uint32_t)((ks*16 + (lane & 7) + 8*((lane >> 3) & 1)) * SW
                                               + (np*16 + (lane >> 4) * 8) * 2));
                    #pragma unroll
                    for (int mf = 0; mf < 2; mf++) {
                        mma16816(C[mf][2*np],     af[mf], bf[0], bf[1]);
                        mma16816(C[mf][2*np + 1], af[mf], bf[2], bf[3]);
                    }
                }
            }
        }
        __syncthreads();   // A2 reads done before sEW overlays

        // ---- EW(+b2) -> smem feature-major sEW[c][edge], stride 128 f32 ----
        #pragma unroll
        for (int mf = 0; mf < 2; mf++) {
            const int rl = m0 + 16*mf + (lane >> 2);
            const int rh = rl + 8;
            #pragma unroll
            for (int nf = 0; nf < 8; nf++) {
                const int c0 = nf*8 + 2*(lane & 3);
                float2 bv = b2p[nf];
                sEW[c0*TE + rl]       = C[mf][nf][0] + bv.x;
                sEW[(c0+1)*TE + rl]   = C[mf][nf][1] + bv.y;
                sEW[c0*TE + rh]       = C[mf][nf][2] + bv.x;
                sEW[(c0+1)*TE + rh]   = C[mf][nf][3] + bv.y;
            }
        }
        __syncthreads();

        // ---- scatter: segmented combine by col, leader-only atomics ----
        #pragma unroll 1
        for (int ec = 0; ec < 4; ec++) {
            const int le = ec*32 + lane;           // tile-local sorted edge
            const int r  = sRow[le];
            const int c  = sCol[le];
            const unsigned mm = __match_any_sync(0xffffffffu, c);
            const int  last   = 31 - __clz((int)mm);
            const bool leader = ((int)(__ffs(mm)) - 1 == lane);
            const float* xr = g_xt + (size_t)r * DD;
            float* sc = g_s + (size_t)c * DD;
            #pragma unroll
            for (int j = 0; j < 8; j++) {
                const int jp = wid * 8 + j;        // feature pair 0..31
                float vx = sEW[(2*jp)*TE + le];
                float vy = sEW[(2*jp+1)*TE + le];
                float2 xv = *(const float2*)(xr + 2*jp);
                vx *= xv.x; vy *= xv.y;
                #pragma unroll
                for (int d = 1; d < 32; d <<= 1) {
                    float ux = __shfl_down_sync(0xffffffffu, vx, d);
                    float uy = __shfl_down_sync(0xffffffffu, vy, d);
                    if (lane + d <= last) { vx += ux; vy += uy; }
                }
                if (leader) red_add_v2(sc + 2*jp, vx, vy);
            }
        }
        __syncthreads();   // protect A1/sRow/sCol/sEW before next tile
    }
}

// ---------------- agg = s / max(cnt,1), in place ---------------------------
__global__ void agg_kernel() {
    int idx = blockIdx.x * 256 + threadIdx.x;
    if (idx >= NN * (DD / 4)) return;
    int node = idx >> 4;
    float inv = 1.0f / fmaxf((float)g_cnti[node], 1.0f);
    float4 v = ((float4*)g_s)[idx];
    v.x *= inv; v.y *= inv; v.z *= inv; v.w *= inv;
    ((float4*)g_s)[idx] = v;
}

// ---------------- batch-norm normalize -------------------------------------
__global__ void bn_kernel(float* __restrict__ outp,
                          const float* __restrict__ gamma,
                          const float* __restrict__ beta)
{
    int idx = blockIdx.x * 256 + threadIdx.x;
    if (idx >= NN * (DD / 4)) return;
    int jb = (idx & 15) * 4;
    float4 h = ((const float4*)g_h)[idx];
    float r[4] = {h.x, h.y, h.z, h.w};
    float rr[4];
    #pragma unroll
    for (int u = 0; u < 4; u++) {
        int j = jb + u;
        double mu  = g_sum[j]   * (1.0 / NN);
        double var = g_sumsq[j] * (1.0 / NN) - mu * mu;
        float  sc  = gamma[j] * rsqrtf(fmaxf((float)var, 0.f) + 1e-5f);
        rr[u] = (float)((double)r[u] - mu) * sc + beta[j];
    }
    ((float4*)outp)[idx] = make_float4(rr[0], rr[1], rr[2], rr[3]);
}

// ---------------- launch ----------------------------------------------------
extern "C" void kernel_launch(void* const* d_in, const int* in_sizes, int n_in,
                              void* d_out, int out_size)
{
    const float* x         = (const float*)d_in[0];
    const float* pos       = (const float*)d_in[1];
    const float* edge_attr = (const float*)d_in[2];
    const int*   row       = (const int*)  d_in[3];
    const int*   col       = (const int*)  d_in[4];
    const float* nW1 = (const float*)d_in[5];
    const float* nb1 = (const float*)d_in[6];
    const float* nW2 = (const float*)d_in[7];
    const float* nb2 = (const float*)d_in[8];
    const float* eW1 = (const float*)d_in[9];
    const float* eb1 = (const float*)d_in[10];
    const float* eW2 = (const float*)d_in[11];
    const float* eb2 = (const float*)d_in[12];
    const float* oW1 = (const float*)d_in[13];
    const float* ob1 = (const float*)d_in[14];
    const float* oW2 = (const float*)d_in[15];
    const float* ob2 = (const float*)d_in[16];
    const float* gam = (const float*)d_in[17];
    const float* bet = (const float*)d_in[18];
    float* outp = (float*)d_out;

    cudaFuncSetAttribute(edge_kernel,
                         cudaFuncAttributeMaxDynamicSharedMemorySize, EDGE_SMEM);

    zero_kernel<<<512, 256>>>();
    count_kernel<<<512, 256>>>(col);
    scan1_kernel<<<SCAN_B, 1024>>>();
    scan2_kernel<<<1, 128>>>();
    scan3_kernel<<<SCAN_B, 1024>>>();
    permute_kernel<<<512, 256>>>(row, col);
    mlp_kernel<false><<<(NN + 127) / 128, 128>>>(x, nW1, nb1, nW2, nb2);
    edge_kernel<<<296, 128, EDGE_SMEM>>>(pos, edge_attr, eW1, eb1, eW2, eb2);
    agg_kernel<<<(NN * (DD / 4) + 255) / 256, 256>>>();
    mlp_kernel<true><<<(NN + 127) / 128, 128>>>(x, oW1, ob1, oW2, ob2);
    bn_kernel<<<(NN * (DD / 4) + 255) / 256, 256>>>(outp, gam, bet);
}

// round 13
// speedup vs baseline: 1.4473x; 1.4473x over previous
#include <cuda_runtime.h>
#include <cuda_bf16.h>
#include <math.h>
#include <stdint.h>

#define NN 100000
#define EE 1600000
#define DD 64
#define EDIM 16
#define SHC 9
#define FEAT 25
#define TE 128            // edges per tile
#define NT (EE / TE)      // 12500

typedef unsigned long long u64;

// ---------------- scratch (device globals) ----------------------------------
__device__ float  g_xt[(size_t)NN * DD];
__device__ float  g_s [(size_t)NN * DD];
__device__ float  g_cnt[NN];
__device__ float  g_h [(size_t)NN * DD];
__device__ double g_sum[DD];
__device__ double g_sumsq[DD];

__device__ __forceinline__ float silu_f(float a) {
    return a / (1.0f + __expf(-a));
}
__device__ __forceinline__ u64 pk2(float x, float y) {
    u64 r; asm("mov.b64 %0, {%1,%2};" : "=l"(r) : "f"(x), "f"(y)); return r;
}
__device__ __forceinline__ void upk2(u64 v, float& x, float& y) {
    asm("mov.b64 {%0,%1}, %2;" : "=f"(x), "=f"(y) : "l"(v));
}
__device__ __forceinline__ void fma2(u64& d, u64 a, u64 b) {
    asm("fma.rn.f32x2 %0, %1, %2, %0;" : "+l"(d) : "l"(a), "l"(b));
}
__device__ __forceinline__ void red_add_v2(float* p, float a, float b) {
    asm volatile("red.global.add.v2.f32 [%0], {%1,%2};"
                 :: "l"(p), "f"(a), "f"(b) : "memory");
}
__device__ __forceinline__ uint32_t s2u(const void* p) {
    uint32_t a;
    asm("{ .reg .u64 t; cvta.to.shared.u64 t, %1; cvt.u32.u64 %0, t; }" : "=r"(a) : "l"(p));
    return a;
}

// ---------------- mma.sync / ldmatrix primitives -----------------------------
__device__ __forceinline__ void ldsm4(uint32_t* r, uint32_t a) {
    asm volatile("ldmatrix.sync.aligned.m8n8.x4.shared.b16 {%0,%1,%2,%3}, [%4];"
                 : "=r"(r[0]), "=r"(r[1]), "=r"(r[2]), "=r"(r[3]) : "r"(a));
}
__device__ __forceinline__ void ldsm4t(uint32_t* r, uint32_t a) {
    asm volatile("ldmatrix.sync.aligned.m8n8.x4.trans.shared.b16 {%0,%1,%2,%3}, [%4];"
                 : "=r"(r[0]), "=r"(r[1]), "=r"(r[2]), "=r"(r[3]) : "r"(a));
}
__device__ __forceinline__ void mma16816(float* c, const uint32_t* a,
                                         uint32_t b0, uint32_t b1) {
    asm volatile(
        "mma.sync.aligned.m16n8k16.row.col.f32.bf16.bf16.f32 "
        "{%0,%1,%2,%3}, {%4,%5,%6,%7}, {%8,%9}, {%0,%1,%2,%3};"
        : "+f"(c[0]), "+f"(c[1]), "+f"(c[2]), "+f"(c[3])
        : "r"(a[0]), "r"(a[1]), "r"(a[2]), "r"(a[3]), "r"(b0), "r"(b1));
}

__device__ __forceinline__ void split8(const float* v, uint4& hi, uint4& lo) {
    uint32_t h[4], l[4];
    #pragma unroll
    for (int p = 0; p < 4; p++) {
        float a = v[2*p], b = v[2*p+1];
        __nv_bfloat162 hh = __floats2bfloat162_rn(a, b);
        float la = a - __bfloat162float(__low2bfloat16(hh));
        float lb = b - __bfloat162float(__high2bfloat16(hh));
        __nv_bfloat162 ll = __floats2bfloat162_rn(la, lb);
        h[p] = *(uint32_t*)&hh; l[p] = *(uint32_t*)&ll;
    }
    hi = make_uint4(h[0], h[1], h[2], h[3]);
    lo = make_uint4(l[0], l[1], l[2], l[3]);
}
__device__ __forceinline__ void split2(float a, float b, uint32_t& hi, uint32_t& lo) {
    __nv_bfloat162 hh = __floats2bfloat162_rn(a, b);
    float la = a - __bfloat162float(__low2bfloat16(hh));
    float lb = b - __bfloat162float(__high2bfloat16(hh));
    __nv_bfloat162 ll = __floats2bfloat162_rn(la, lb);
    hi = *(uint32_t*)&hh; lo = *(uint32_t*)&ll;
}

// ---------------- zero scratch + dummy (ncu launch-slot shim) ----------------
__global__ void zero_kernel() {
    int idx = blockIdx.x * blockDim.x + threadIdx.x;
    int stride = gridDim.x * blockDim.x;
    float4 z = make_float4(0.f, 0.f, 0.f, 0.f);
    for (int i = idx; i < NN * (DD / 4); i += stride)
        ((float4*)g_s)[i] = z;
    for (int i = idx; i < NN; i += stride)
        g_cnt[i] = 0.f;
    if (idx < DD) { g_sum[idx] = 0.0; g_sumsq[idx] = 0.0; }
}
__global__ void dummy_kernel() {}   // shifts edge_kernel into the profiled slot

// ---------------- node / output MLP (R5, unchanged) --------------------------
template <bool IS_OUT>
__global__ __launch_bounds__(128)
void mlp_kernel(const float* __restrict__ x,
                const float* __restrict__ W1, const float* __restrict__ b1,
                const float* __restrict__ W2, const float* __restrict__ b2)
{
    constexpr int IND = IS_OUT ? 128 : 64;
    __shared__ __align__(16) float sW1[IND * DD];
    __shared__ __align__(16) float sW2[DD * DD];
    const int t = threadIdx.x;
    for (int i = t; i < IND * DD; i += 128) sW1[i] = W1[i];
    for (int i = t; i < DD * DD;  i += 128) sW2[i] = W2[i];
    __syncthreads();

    const int id = blockIdx.x * 128 + t;
    const bool valid = (id < NN);
    const int rid = valid ? id : (NN - 1);

    const float4* rowA;
    const float4* rowB = nullptr;
    if (IS_OUT) {
        rowA = (const float4*)(g_s + (size_t)rid * DD);
        rowB = (const float4*)(x   + (size_t)rid * DD);
    } else {
        rowA = (const float4*)(x + (size_t)rid * DD);
    }

    u64 outp[32];
    {
        const ulonglong2* b2v = (const ulonglong2*)b2;
        #pragma unroll
        for (int q = 0; q < 16; q++) { ulonglong2 bv = b2v[q]; outp[2*q] = bv.x; outp[2*q+1] = bv.y; }
    }

    #pragma unroll 1
    for (int ch = 0; ch < 4; ch++) {
        const int base = ch * 16;
        u64 hp[8];
        {
            const ulonglong2* b1v = (const ulonglong2*)(b1 + base);
            #pragma unroll
            for (int q = 0; q < 4; q++) { ulonglong2 bv = b1v[q]; hp[2*q] = bv.x; hp[2*q+1] = bv.y; }
        }
        #pragma unroll 2
        for (int g = 0; g < IND / 4; g++) {
            float4 v;
            if (IS_OUT) v = (g < 16) ? rowA[g] : rowB[g - 16];
            else        v = rowA[g];
            const float fv[4] = {v.x, v.y, v.z, v.w};
            #pragma unroll
            for (int u = 0; u < 4; u++) {
                const u64 fmp = pk2(fv[u], fv[u]);
                const ulonglong2* wr = (const ulonglong2*)(sW1 + (g*4 + u) * DD + base);
                #pragma unroll
                for (int q = 0; q < 4; q++) {
                    ulonglong2 w = wr[q];
                    fma2(hp[2*q], fmp, w.x);
                    fma2(hp[2*q+1], fmp, w.y);
                }
            }
        }
        float h16[16];
        #pragma unroll
        for (int i = 0; i < 8; i++) {
            float a, b; upk2(hp[i], a, b);
            h16[2*i] = silu_f(a); h16[2*i+1] = silu_f(b);
        }
        #pragma unroll
        for (int kk = 0; kk < 16; kk++) {
            const u64 hvp = pk2(h16[kk], h16[kk]);
            const ulonglong2* wr = (const ulonglong2*)(sW2 + (base + kk) * DD);
            #pragma unroll
            for (int q = 0; q < 16; q++) {
                ulonglong2 w = wr[q];
                fma2(outp[2*q], hvp, w.x);
                fma2(outp[2*q+1], hvp, w.y);
            }
        }
    }

    float* dst = IS_OUT ? g_h : g_xt;
    if (valid) {
        ulonglong2* o = (ulonglong2*)(dst + (size_t)id * DD);
        #pragma unroll
        for (int q = 0; q < 16; q++) {
            ulonglong2 w; w.x = outp[2*q]; w.y = outp[2*q+1];
            o[q] = w;
        }
    }

    if (IS_OUT) {
        #pragma unroll
        for (int jp = 0; jp < 32; jp++) {
            float va, vb; upk2(outp[jp], va, vb);
            if (!valid) { va = 0.f; vb = 0.f; }
            float s0 = va, q0 = va * va, s1 = vb, q1 = vb * vb;
            #pragma unroll
            for (int o = 16; o; o >>= 1) {
                s0 += __shfl_down_sync(0xffffffffu, s0, o);
                q0 += __shfl_down_sync(0xffffffffu, q0, o);
                s1 += __shfl_down_sync(0xffffffffu, s1, o);
                q1 += __shfl_down_sync(0xffffffffu, q1, o);
            }
            if ((t & 31) == 0) {
                atomicAdd(&g_sum[2*jp],     (double)s0);
                atomicAdd(&g_sumsq[2*jp],   (double)q0);
                atomicAdd(&g_sum[2*jp+1],   (double)s1);
                atomicAdd(&g_sumsq[2*jp+1], (double)q1);
            }
        }
    }
}

// ---------------- fused edge kernel: fragment-chained HMMA -------------------
// Warp-private 32-edge sub-tiles (R11) + GEMM1 C-fragments reused DIRECTLY as
// GEMM2 A-fragments (m16n8 C layout == m16k16 A layout after bf16x2 packing):
// no H staging in smem -> smem 49.4 KB -> 3+ blocks/SM (12 warps, was 8).
#define SA1 80
#define SW  144
#define OFF_B2   0
#define OFF_ROW  256
#define OFF_COL  768
#define OFF_A1H  1280
#define OFF_A1L  11520
#define OFF_W1H  21760
#define OFF_W1L  26368
#define OFF_W2H  30976
#define OFF_W2L  40192
#define EDGE_SMEM 49408

__global__ __launch_bounds__(128, 3)
void edge_kernel(const float* __restrict__ pos,
                 const float* __restrict__ edge_attr,
                 const int*   __restrict__ row,
                 const int*   __restrict__ col,
                 const float* __restrict__ W1, const float* __restrict__ b1,
                 const float* __restrict__ W2, const float* __restrict__ b2)
{
    extern __shared__ __align__(16) char smem[];
    const uint32_t sb = s2u(smem);
    const int t    = threadIdx.x;
    const int wid  = t >> 5;
    const int lane = t & 31;
    const int m0   = wid * 32;

    float* sB2  = (float*)(smem + OFF_B2);
    int*   sRow = (int*)(smem + OFF_ROW);
    int*   sCol = (int*)(smem + OFF_COL);

    // ---- one-time: weights -> bf16 hi/lo, [k][n] row-major, stride SW ----
    for (int i = t; i < 32 * 64; i += 128) {
        int k = i >> 6, n = i & 63;
        float v = (k < FEAT) ? W1[k * 64 + n] : ((k == FEAT) ? b1[n] : 0.f);
        uint32_t o = (uint32_t)(k * SW + n * 2);
        __nv_bfloat16 h = __float2bfloat16(v);
        *(__nv_bfloat16*)(smem + OFF_W1H + o) = h;
        *(__nv_bfloat16*)(smem + OFF_W1L + o) = __float2bfloat16(v - __bfloat162float(h));
    }
    for (int i = t; i < 64 * 64; i += 128) {
        int k = i >> 6, n = i & 63;
        float v = W2[k * 64 + n];
        uint32_t o = (uint32_t)(k * SW + n * 2);
        __nv_bfloat16 h = __float2bfloat16(v);
        *(__nv_bfloat16*)(smem + OFF_W2H + o) = h;
        *(__nv_bfloat16*)(smem + OFF_W2L + o) = __float2bfloat16(v - __bfloat162float(h));
    }
    if (t < 64) sB2[t] = b2[t];
    __syncthreads();

    float2 b2p[8];
    {
        const int cb = 2 * (lane & 3);
        #pragma unroll
        for (int nf = 0; nf < 8; nf++)
            b2p[nf] = *(float2*)(sB2 + nf*8 + cb);
    }

    const uint32_t aA1H = sb + OFF_A1H, aA1L = sb + OFF_A1L;
    const uint32_t aW1H = sb + OFF_W1H, aW1L = sb + OFF_W1L;
    const uint32_t aW2H = sb + OFF_W2H, aW2L = sb + OFF_W2L;

    for (int tile = blockIdx.x; tile < NT; tile += gridDim.x) {
        const int e = tile * TE + t;

        // ---- phase 1: per-edge features (bf16 hi/lo) -> A1 row t ----
        {
            const int r = row[e];
            const int c = col[e];
            sRow[t] = r; sCol[t] = c;

            float px = pos[3*r]   - pos[3*c];
            float py = pos[3*r+1] - pos[3*c+1];
            float pz = pos[3*r+2] - pos[3*c+2];
            float len = sqrtf(px*px + py*py + pz*pz + 1e-12f);
            float dx = px / len, dy = py / len, dz = pz / len;
            float n2 = sqrtf(dx*dx + dy*dy + dz*dz) + 1e-10f;
            dx /= n2; dy /= n2; dz /= n2;

            float f[32];
            f[0] = 0.28209479177387814f;
            f[1] = 0.4886025119029199f * dy;
            f[2] = 0.4886025119029199f * dz;
            f[3] = 0.4886025119029199f * dx;
            f[4] = 1.0925484305920792f * dx * dy;
            f[5] = 1.0925484305920792f * dy * dz;
            f[6] = 0.31539156525252005f * (3.0f * dz * dz - 1.0f);
            f[7] = 1.0925484305920792f * dx * dz;
            f[8] = 0.5462742152960396f * (dx*dx - dy*dy);
            const float4* ea = (const float4*)(edge_attr + (size_t)e * EDIM);
            #pragma unroll
            for (int i = 0; i < 4; i++) {
                float4 v = ea[i];
                f[SHC + 4*i]   = v.x; f[SHC + 4*i+1] = v.y;
                f[SHC + 4*i+2] = v.z; f[SHC + 4*i+3] = v.w;
            }
            f[25] = 1.0f;
            #pragma unroll
            for (int k = 26; k < 32; k++) f[k] = 0.f;

            #pragma unroll
            for (int cc = 0; cc < 4; cc++) {
                uint4 hi, lo;
                split8(f + cc*8, hi, lo);
                *(uint4*)(smem + OFF_A1H + t*SA1 + cc*16) = hi;
                *(uint4*)(smem + OFF_A1L + t*SA1 + cc*16) = lo;
            }
            atomicAdd(&g_cnt[c], 1.0f);
        }
        __syncwarp();

        // ---- GEMM1: K=32, 3 passes, C in f32 ----
        float C[2][8][4];
        #pragma unroll
        for (int mf = 0; mf < 2; mf++)
            #pragma unroll
            for (int nf = 0; nf < 8; nf++)
                #pragma unroll
                for (int q = 0; q < 4; q++) C[mf][nf][q] = 0.f;

        #pragma unroll
        for (int pass = 0; pass < 3; pass++) {
            const uint32_t Ab = (pass == 2) ? aA1L : aA1H;
            const uint32_t Wb = (pass == 1) ? aW1L : aW1H;
            #pragma unroll
            for (int ks = 0; ks < 2; ks++) {
                uint32_t af[2][4];
                #pragma unroll
                for (int mf = 0; mf < 2; mf++)
                    ldsm4(af[mf], Ab + (uint32_t)((m0 + 16*mf + (lane & 15)) * SA1
                                                  + ks*32 + (lane >> 4) * 16));
                #pragma unroll
                for (int np = 0; np < 4; np++) {
                    uint32_t bf[4];
                    ldsm4t(bf, Wb + (uint32_t)((ks*16 + (lane & 7) + 8*((lane >> 3) & 1)) * SW
                                               + (np*16 + (lane >> 4) * 8) * 2));
                    #pragma unroll
                    for (int mf = 0; mf < 2; mf++) {
                        mma16816(C[mf][2*np],     af[mf], bf[0], bf[1]);
                        mma16816(C[mf][2*np + 1], af[mf], bf[2], bf[3]);
                    }
                }
            }
        }

        // ---- silu + pack C1 -> A2 fragments (hi/lo), all in registers ----
        // A-frag for k-block kb: a0=pack(C[mf][2kb][0],[1]) a1=pack([2],[3])
        //                        a2=pack(C[mf][2kb+1][0],[1]) a3=pack([2],[3])
        uint32_t AH[2][4][4], AL[2][4][4];
        #pragma unroll
        for (int mf = 0; mf < 2; mf++)
            #pragma unroll
            for (int kb = 0; kb < 4; kb++) {
                float s00 = silu_f(C[mf][2*kb][0]),   s01 = silu_f(C[mf][2*kb][1]);
                float s02 = silu_f(C[mf][2*kb][2]),   s03 = silu_f(C[mf][2*kb][3]);
                float s10 = silu_f(C[mf][2*kb+1][0]), s11 = silu_f(C[mf][2*kb+1][1]);
                float s12 = silu_f(C[mf][2*kb+1][2]), s13 = silu_f(C[mf][2*kb+1][3]);
                split2(s00, s01, AH[mf][kb][0], AL[mf][kb][0]);
                split2(s02, s03, AH[mf][kb][1], AL[mf][kb][1]);
                split2(s10, s11, AH[mf][kb][2], AL[mf][kb][2]);
                split2(s12, s13, AH[mf][kb][3], AL[mf][kb][3]);
            }

        // ---- GEMM2: K=64, 3 passes, A from fragments ----
        #pragma unroll
        for (int mf = 0; mf < 2; mf++)
            #pragma unroll
            for (int nf = 0; nf < 8; nf++)
                #pragma unroll
                for (int q = 0; q < 4; q++) C[mf][nf][q] = 0.f;

        #pragma unroll
        for (int pass = 0; pass < 3; pass++) {
            const uint32_t Wb = (pass == 1) ? aW2L : aW2H;
            const bool useLo = (pass == 2);
            #pragma unroll
            for (int kb = 0; kb < 4; kb++) {
                #pragma unroll
                for (int np = 0; np < 4; np++) {
                    uint32_t bf[4];
                    ldsm4t(bf, Wb + (uint32_t)((kb*16 + (lane & 7) + 8*((lane >> 3) & 1)) * SW
                                               + (np*16 + (lane >> 4) * 8) * 2));
                    #pragma unroll
                    for (int mf = 0; mf < 2; mf++) {
                        const uint32_t* af = useLo ? AL[mf][kb] : AH[mf][kb];
                        mma16816(C[mf][2*np],     af, bf[0], bf[1]);
                        mma16816(C[mf][2*np + 1], af, bf[2], bf[3]);
                    }
                }
            }
        }

        // ---- scatter straight from fragments (unsorted, red.v2) ----
        #pragma unroll
        for (int mf = 0; mf < 2; mf++) {
            const int rl = m0 + 16*mf + (lane >> 2);
            const int rh = rl + 8;
            const int nrl = sRow[rl], ncl = sCol[rl];
            const int nrh = sRow[rh], nch = sCol[rh];
            const float* xl = g_xt + (size_t)nrl * DD;
            const float* xh = g_xt + (size_t)nrh * DD;
            float* sl = g_s + (size_t)ncl * DD;
            float* sh = g_s + (size_t)nch * DD;
            const int cb = 2 * (lane & 3);
            #pragma unroll
            for (int nf = 0; nf < 8; nf++) {
                const int c0 = nf*8 + cb;
                float2 bv = b2p[nf];
                float2 xv = *(const float2*)(xl + c0);
                red_add_v2(sl + c0, (C[mf][nf][0] + bv.x) * xv.x,
                                    (C[mf][nf][1] + bv.y) * xv.y);
                float2 xv2 = *(const float2*)(xh + c0);
                red_add_v2(sh + c0, (C[mf][nf][2] + bv.x) * xv2.x,
                                    (C[mf][nf][3] + bv.y) * xv2.y);
            }
        }
        __syncwarp();   // protect A1/sRow/sCol (warp-private) before next tile
    }
}

// ---------------- agg = s / max(cnt,1), in place ---------------------------
__global__ void agg_kernel() {
    int idx = blockIdx.x * 256 + threadIdx.x;
    if (idx >= NN * (DD / 4)) return;
    int node = idx >> 4;
    float inv = 1.0f / fmaxf(g_cnt[node], 1.0f);
    float4 v = ((float4*)g_s)[idx];
    v.x *= inv; v.y *= inv; v.z *= inv; v.w *= inv;
    ((float4*)g_s)[idx] = v;
}

// ---------------- batch-norm normalize -------------------------------------
__global__ void bn_kernel(float* __restrict__ outp,
                          const float* __restrict__ gamma,
                          const float* __restrict__ beta)
{
    int idx = blockIdx.x * 256 + threadIdx.x;
    if (idx >= NN * (DD / 4)) return;
    int jb = (idx & 15) * 4;
    float4 h = ((const float4*)g_h)[idx];
    float r[4] = {h.x, h.y, h.z, h.w};
    float rr[4];
    #pragma unroll
    for (int u = 0; u < 4; u++) {
        int j = jb + u;
        double mu  = g_sum[j]   * (1.0 / NN);
        double var = g_sumsq[j] * (1.0 / NN) - mu * mu;
        float  sc  = gamma[j] * rsqrtf(fmaxf((float)var, 0.f) + 1e-5f);
        rr[u] = (float)((double)r[u] - mu) * sc + beta[j];
    }
    ((float4*)outp)[idx] = make_float4(rr[0], rr[1], rr[2], rr[3]);
}

// ---------------- launch ----------------------------------------------------
extern "C" void kernel_launch(void* const* d_in, const int* in_sizes, int n_in,
                              void* d_out, int out_size)
{
    const float* x         = (const float*)d_in[0];
    const float* pos       = (const float*)d_in[1];
    const float* edge_attr = (const float*)d_in[2];
    const int*   row       = (const int*)  d_in[3];
    const int*   col       = (const int*)  d_in[4];
    const float* nW1 = (const float*)d_in[5];
    const float* nb1 = (const float*)d_in[6];
    const float* nW2 = (const float*)d_in[7];
    const float* nb2 = (const float*)d_in[8];
    const float* eW1 = (const float*)d_in[9];
    const float* eb1 = (const float*)d_in[10];
    const float* eW2 = (const float*)d_in[11];
    const float* eb2 = (const float*)d_in[12];
    const float* oW1 = (const float*)d_in[13];
    const float* ob1 = (const float*)d_in[14];
    const float* oW2 = (const float*)d_in[15];
    const float* ob2 = (const float*)d_in[16];
    const float* gam = (const float*)d_in[17];
    const float* bet = (const float*)d_in[18];
    float* outp = (float*)d_out;

    cudaFuncSetAttribute(edge_kernel,
                         cudaFuncAttributeMaxDynamicSharedMemorySize, EDGE_SMEM);

    zero_kernel<<<512, 256>>>();                                   // launch 1
    mlp_kernel<false><<<(NN + 127) / 128, 128>>>(x, nW1, nb1, nW2, nb2);  // 2
    dummy_kernel<<<1, 32>>>();                                     // 3 (shim)
    edge_kernel<<<444, 128, EDGE_SMEM>>>(pos, edge_attr, row, col,
                                         eW1, eb1, eW2, eb2);      // 4 <- profiled
    agg_kernel<<<(NN * (DD / 4) + 255) / 256, 256>>>();            // 5
    mlp_kernel<true><<<(NN + 127) / 128, 128>>>(x, oW1, ob1, oW2, ob2);   // 6
    bn_kernel<<<(NN * (DD / 4) + 255) / 256, 256>>>(outp, gam, bet);      // 7
}

// round 14
// speedup vs baseline: 1.5655x; 1.0817x over previous
#include <cuda_runtime.h>
#include <cuda_bf16.h>
#include <math.h>
#include <stdint.h>

#define NN 100000
#define EE 1600000
#define DD 64
#define EDIM 16
#define SHC 9
#define FEAT 25
#define TE 128            // edges per tile
#define NT (EE / TE)      // 12500

typedef unsigned long long u64;

// ---------------- scratch (device globals) ----------------------------------
__device__ float  g_xt[(size_t)NN * DD];
__device__ float  g_s [(size_t)NN * DD];
__device__ float  g_cnt[NN];
__device__ float  g_h [(size_t)NN * DD];
__device__ double g_sum[DD];
__device__ double g_sumsq[DD];

__device__ __forceinline__ float silu_f(float a) {
    return a / (1.0f + __expf(-a));
}
__device__ __forceinline__ u64 pk2(float x, float y) {
    u64 r; asm("mov.b64 %0, {%1,%2};" : "=l"(r) : "f"(x), "f"(y)); return r;
}
__device__ __forceinline__ void upk2(u64 v, float& x, float& y) {
    asm("mov.b64 {%0,%1}, %2;" : "=f"(x), "=f"(y) : "l"(v));
}
__device__ __forceinline__ void fma2(u64& d, u64 a, u64 b) {
    asm("fma.rn.f32x2 %0, %1, %2, %0;" : "+l"(d) : "l"(a), "l"(b));
}
__device__ __forceinline__ void red_add_v2(float* p, float a, float b) {
    asm volatile("red.global.add.v2.f32 [%0], {%1,%2};"
                 :: "l"(p), "f"(a), "f"(b) : "memory");
}
__device__ __forceinline__ uint32_t s2u(const void* p) {
    uint32_t a;
    asm("{ .reg .u64 t; cvta.to.shared.u64 t, %1; cvt.u32.u64 %0, t; }" : "=r"(a) : "l"(p));
    return a;
}

// ---------------- mma.sync / ldmatrix primitives -----------------------------
__device__ __forceinline__ void ldsm4(uint32_t* r, uint32_t a) {
    asm volatile("ldmatrix.sync.aligned.m8n8.x4.shared.b16 {%0,%1,%2,%3}, [%4];"
                 : "=r"(r[0]), "=r"(r[1]), "=r"(r[2]), "=r"(r[3]) : "r"(a));
}
__device__ __forceinline__ void ldsm4t(uint32_t* r, uint32_t a) {
    asm volatile("ldmatrix.sync.aligned.m8n8.x4.trans.shared.b16 {%0,%1,%2,%3}, [%4];"
                 : "=r"(r[0]), "=r"(r[1]), "=r"(r[2]), "=r"(r[3]) : "r"(a));
}
__device__ __forceinline__ void mma16816(float* c, const uint32_t* a,
                                         uint32_t b0, uint32_t b1) {
    asm volatile(
        "mma.sync.aligned.m16n8k16.row.col.f32.bf16.bf16.f32 "
        "{%0,%1,%2,%3}, {%4,%5,%6,%7}, {%8,%9}, {%0,%1,%2,%3};"
        : "+f"(c[0]), "+f"(c[1]), "+f"(c[2]), "+f"(c[3])
        : "r"(a[0]), "r"(a[1]), "r"(a[2]), "r"(a[3]), "r"(b0), "r"(b1));
}

__device__ __forceinline__ void split8(const float* v, uint4& hi, uint4& lo) {
    uint32_t h[4], l[4];
    #pragma unroll
    for (int p = 0; p < 4; p++) {
        float a = v[2*p], b = v[2*p+1];
        __nv_bfloat162 hh = __floats2bfloat162_rn(a, b);
        float la = a - __bfloat162float(__low2bfloat16(hh));
        float lb = b - __bfloat162float(__high2bfloat16(hh));
        __nv_bfloat162 ll = __floats2bfloat162_rn(la, lb);
        h[p] = *(uint32_t*)&hh; l[p] = *(uint32_t*)&ll;
    }
    hi = make_uint4(h[0], h[1], h[2], h[3]);
    lo = make_uint4(l[0], l[1], l[2], l[3]);
}
__device__ __forceinline__ void split2(float a, float b, uint32_t& hi, uint32_t& lo) {
    __nv_bfloat162 hh = __floats2bfloat162_rn(a, b);
    float la = a - __bfloat162float(__low2bfloat16(hh));
    float lb = b - __bfloat162float(__high2bfloat16(hh));
    __nv_bfloat162 ll = __floats2bfloat162_rn(la, lb);
    hi = *(uint32_t*)&hh; lo = *(uint32_t*)&ll;
}

// ---------------- zero scratch + dummy (ncu launch-slot shim) ----------------
__global__ void zero_kernel() {
    int idx = blockIdx.x * blockDim.x + threadIdx.x;
    int stride = gridDim.x * blockDim.x;
    float4 z = make_float4(0.f, 0.f, 0.f, 0.f);
    for (int i = idx; i < NN * (DD / 4); i += stride)
        ((float4*)g_s)[i] = z;
    for (int i = idx; i < NN; i += stride)
        g_cnt[i] = 0.f;
    if (idx < DD) { g_sum[idx] = 0.0; g_sumsq[idx] = 0.0; }
}
__global__ void dummy_kernel() {}   // keeps edge_kernel in the profiled slot

// ---------------- node / output MLP (R5, unchanged) --------------------------
template <bool IS_OUT>
__global__ __launch_bounds__(128)
void mlp_kernel(const float* __restrict__ x,
                const float* __restrict__ W1, const float* __restrict__ b1,
                const float* __restrict__ W2, const float* __restrict__ b2)
{
    constexpr int IND = IS_OUT ? 128 : 64;
    __shared__ __align__(16) float sW1[IND * DD];
    __shared__ __align__(16) float sW2[DD * DD];
    const int t = threadIdx.x;
    for (int i = t; i < IND * DD; i += 128) sW1[i] = W1[i];
    for (int i = t; i < DD * DD;  i += 128) sW2[i] = W2[i];
    __syncthreads();

    const int id = blockIdx.x * 128 + t;
    const bool valid = (id < NN);
    const int rid = valid ? id : (NN - 1);

    const float4* rowA;
    const float4* rowB = nullptr;
    if (IS_OUT) {
        rowA = (const float4*)(g_s + (size_t)rid * DD);
        rowB = (const float4*)(x   + (size_t)rid * DD);
    } else {
        rowA = (const float4*)(x + (size_t)rid * DD);
    }

    u64 outp[32];
    {
        const ulonglong2* b2v = (const ulonglong2*)b2;
        #pragma unroll
        for (int q = 0; q < 16; q++) { ulonglong2 bv = b2v[q]; outp[2*q] = bv.x; outp[2*q+1] = bv.y; }
    }

    #pragma unroll 1
    for (int ch = 0; ch < 4; ch++) {
        const int base = ch * 16;
        u64 hp[8];
        {
            const ulonglong2* b1v = (const ulonglong2*)(b1 + base);
            #pragma unroll
            for (int q = 0; q < 4; q++) { ulonglong2 bv = b1v[q]; hp[2*q] = bv.x; hp[2*q+1] = bv.y; }
        }
        #pragma unroll 2
        for (int g = 0; g < IND / 4; g++) {
            float4 v;
            if (IS_OUT) v = (g < 16) ? rowA[g] : rowB[g - 16];
            else        v = rowA[g];
            const float fv[4] = {v.x, v.y, v.z, v.w};
            #pragma unroll
            for (int u = 0; u < 4; u++) {
                const u64 fmp = pk2(fv[u], fv[u]);
                const ulonglong2* wr = (const ulonglong2*)(sW1 + (g*4 + u) * DD + base);
                #pragma unroll
                for (int q = 0; q < 4; q++) {
                    ulonglong2 w = wr[q];
                    fma2(hp[2*q], fmp, w.x);
                    fma2(hp[2*q+1], fmp, w.y);
                }
            }
        }
        float h16[16];
        #pragma unroll
        for (int i = 0; i < 8; i++) {
            float a, b; upk2(hp[i], a, b);
            h16[2*i] = silu_f(a); h16[2*i+1] = silu_f(b);
        }
        #pragma unroll
        for (int kk = 0; kk < 16; kk++) {
            const u64 hvp = pk2(h16[kk], h16[kk]);
            const ulonglong2* wr = (const ulonglong2*)(sW2 + (base + kk) * DD);
            #pragma unroll
            for (int q = 0; q < 16; q++) {
                ulonglong2 w = wr[q];
                fma2(outp[2*q], hvp, w.x);
                fma2(outp[2*q+1], hvp, w.y);
            }
        }
    }

    float* dst = IS_OUT ? g_h : g_xt;
    if (valid) {
        ulonglong2* o = (ulonglong2*)(dst + (size_t)id * DD);
        #pragma unroll
        for (int q = 0; q < 16; q++) {
            ulonglong2 w; w.x = outp[2*q]; w.y = outp[2*q+1];
            o[q] = w;
        }
    }

    if (IS_OUT) {
        #pragma unroll
        for (int jp = 0; jp < 32; jp++) {
            float va, vb; upk2(outp[jp], va, vb);
            if (!valid) { va = 0.f; vb = 0.f; }
            float s0 = va, q0 = va * va, s1 = vb, q1 = vb * vb;
            #pragma unroll
            for (int o = 16; o; o >>= 1) {
                s0 += __shfl_down_sync(0xffffffffu, s0, o);
                q0 += __shfl_down_sync(0xffffffffu, q0, o);
                s1 += __shfl_down_sync(0xffffffffu, s1, o);
                q1 += __shfl_down_sync(0xffffffffu, q1, o);
            }
            if ((t & 31) == 0) {
                atomicAdd(&g_sum[2*jp],     (double)s0);
                atomicAdd(&g_sumsq[2*jp],   (double)q0);
                atomicAdd(&g_sum[2*jp+1],   (double)s1);
                atomicAdd(&g_sumsq[2*jp+1], (double)q1);
            }
        }
    }
}

// ---------------- fused edge kernel: fragment-chained HMMA, 4 blocks/SM ------
// R13 + AL spilled to the dead A1 smem region during GEMM2 (stride 144 ->
// conflict-free STS/LDS.128) and b2 read from smem at scatter: peak regs
// ~115 -> __launch_bounds__(128,4) -> 16 warps/SM (was 12, occ 18.4%).
#define SA1 80
#define SW  144
#define SSP 144              // AL spill stride (bytes per thread)
#define OFF_B2   0
#define OFF_ROW  256
#define OFF_COL  768
#define OFF_A1H  1280
#define OFF_A1L  11520
#define OFF_SPILL OFF_A1H    // overlays A1 (dead after GEMM1); 128*144=18432<=20480
#define OFF_W1H  21760
#define OFF_W1L  26368
#define OFF_W2H  30976
#define OFF_W2L  40192
#define EDGE_SMEM 49408

__global__ __launch_bounds__(128, 4)
void edge_kernel(const float* __restrict__ pos,
                 const float* __restrict__ edge_attr,
                 const int*   __restrict__ row,
                 const int*   __restrict__ col,
                 const float* __restrict__ W1, const float* __restrict__ b1,
                 const float* __restrict__ W2, const float* __restrict__ b2)
{
    extern __shared__ __align__(16) char smem[];
    const uint32_t sb = s2u(smem);
    const int t    = threadIdx.x;
    const int wid  = t >> 5;
    const int lane = t & 31;
    const int m0   = wid * 32;

    float* sB2  = (float*)(smem + OFF_B2);
    int*   sRow = (int*)(smem + OFF_ROW);
    int*   sCol = (int*)(smem + OFF_COL);

    // ---- one-time: weights -> bf16 hi/lo, [k][n] row-major, stride SW ----
    for (int i = t; i < 32 * 64; i += 128) {
        int k = i >> 6, n = i & 63;
        float v = (k < FEAT) ? W1[k * 64 + n] : ((k == FEAT) ? b1[n] : 0.f);
        uint32_t o = (uint32_t)(k * SW + n * 2);
        __nv_bfloat16 h = __float2bfloat16(v);
        *(__nv_bfloat16*)(smem + OFF_W1H + o) = h;
        *(__nv_bfloat16*)(smem + OFF_W1L + o) = __float2bfloat16(v - __bfloat162float(h));
    }
    for (int i = t; i < 64 * 64; i += 128) {
        int k = i >> 6, n = i & 63;
        float v = W2[k * 64 + n];
        uint32_t o = (uint32_t)(k * SW + n * 2);
        __nv_bfloat16 h = __float2bfloat16(v);
        *(__nv_bfloat16*)(smem + OFF_W2H + o) = h;
        *(__nv_bfloat16*)(smem + OFF_W2L + o) = __float2bfloat16(v - __bfloat162float(h));
    }
    if (t < 64) sB2[t] = b2[t];
    __syncthreads();

    const uint32_t aA1H = sb + OFF_A1H, aA1L = sb + OFF_A1L;
    const uint32_t aW1H = sb + OFF_W1H, aW1L = sb + OFF_W1L;
    const uint32_t aW2H = sb + OFF_W2H, aW2L = sb + OFF_W2L;

    for (int tile = blockIdx.x; tile < NT; tile += gridDim.x) {
        const int e = tile * TE + t;

        // ---- phase 1: per-edge features (bf16 hi/lo) -> A1 row t ----
        {
            const int r = row[e];
            const int c = col[e];
            sRow[t] = r; sCol[t] = c;

            float px = pos[3*r]   - pos[3*c];
            float py = pos[3*r+1] - pos[3*c+1];
            float pz = pos[3*r+2] - pos[3*c+2];
            float len = sqrtf(px*px + py*py + pz*pz + 1e-12f);
            float dx = px / len, dy = py / len, dz = pz / len;
            float n2 = sqrtf(dx*dx + dy*dy + dz*dz) + 1e-10f;
            dx /= n2; dy /= n2; dz /= n2;

            float f[32];
            f[0] = 0.28209479177387814f;
            f[1] = 0.4886025119029199f * dy;
            f[2] = 0.4886025119029199f * dz;
            f[3] = 0.4886025119029199f * dx;
            f[4] = 1.0925484305920792f * dx * dy;
            f[5] = 1.0925484305920792f * dy * dz;
            f[6] = 0.31539156525252005f * (3.0f * dz * dz - 1.0f);
            f[7] = 1.0925484305920792f * dx * dz;
            f[8] = 0.5462742152960396f * (dx*dx - dy*dy);
            const float4* ea = (const float4*)(edge_attr + (size_t)e * EDIM);
            #pragma unroll
            for (int i = 0; i < 4; i++) {
                float4 v = ea[i];
                f[SHC + 4*i]   = v.x; f[SHC + 4*i+1] = v.y;
                f[SHC + 4*i+2] = v.z; f[SHC + 4*i+3] = v.w;
            }
            f[25] = 1.0f;
            #pragma unroll
            for (int k = 26; k < 32; k++) f[k] = 0.f;

            #pragma unroll
            for (int cc = 0; cc < 4; cc++) {
                uint4 hi, lo;
                split8(f + cc*8, hi, lo);
                *(uint4*)(smem + OFF_A1H + t*SA1 + cc*16) = hi;
                *(uint4*)(smem + OFF_A1L + t*SA1 + cc*16) = lo;
            }
            atomicAdd(&g_cnt[c], 1.0f);
        }
        __syncwarp();    // A1 rows are warp-private

        // ---- GEMM1: K=32, 3 passes, C in f32 ----
        float C[2][8][4];
        #pragma unroll
        for (int mf = 0; mf < 2; mf++)
            #pragma unroll
            for (int nf = 0; nf < 8; nf++)
                #pragma unroll
                for (int q = 0; q < 4; q++) C[mf][nf][q] = 0.f;

        #pragma unroll
        for (int pass = 0; pass < 3; pass++) {
            const uint32_t Ab = (pass == 2) ? aA1L : aA1H;
            const uint32_t Wb = (pass == 1) ? aW1L : aW1H;
            #pragma unroll
            for (int ks = 0; ks < 2; ks++) {
                uint32_t af[2][4];
                #pragma unroll
                for (int mf = 0; mf < 2; mf++)
                    ldsm4(af[mf], Ab + (uint32_t)((m0 + 16*mf + (lane & 15)) * SA1
                                                  + ks*32 + (lane >> 4) * 16));
                #pragma unroll
                for (int np = 0; np < 4; np++) {
                    uint32_t bf[4];
                    ldsm4t(bf, Wb + (uint32_t)((ks*16 + (lane & 7) + 8*((lane >> 3) & 1)) * SW
                                               + (np*16 + (lane >> 4) * 8) * 2));
                    #pragma unroll
                    for (int mf = 0; mf < 2; mf++) {
                        mma16816(C[mf][2*np],     af[mf], bf[0], bf[1]);
                        mma16816(C[mf][2*np + 1], af[mf], bf[2], bf[3]);
                    }
                }
            }
        }
        __syncthreads();   // ALL warps' A1 reads done before spill overlays A1

        // ---- silu + pack: AH kept in regs, AL spilled to smem scratch ----
        uint32_t AH[2][4][4];
        {
            const uint32_t spill = sb + OFF_SPILL + (uint32_t)(t * SSP);
            #pragma unroll
            for (int mf = 0; mf < 2; mf++)
                #pragma unroll
                for (int kb = 0; kb < 4; kb++) {
                    float s00 = silu_f(C[mf][2*kb][0]),   s01 = silu_f(C[mf][2*kb][1]);
                    float s02 = silu_f(C[mf][2*kb][2]),   s03 = silu_f(C[mf][2*kb][3]);
                    float s10 = silu_f(C[mf][2*kb+1][0]), s11 = silu_f(C[mf][2*kb+1][1]);
                    float s12 = silu_f(C[mf][2*kb+1][2]), s13 = silu_f(C[mf][2*kb+1][3]);
                    uint4 alv;
                    split2(s00, s01, AH[mf][kb][0], alv.x);
                    split2(s02, s03, AH[mf][kb][1], alv.y);
                    split2(s10, s11, AH[mf][kb][2], alv.z);
                    split2(s12, s13, AH[mf][kb][3], alv.w);
                    asm volatile("st.shared.v4.b32 [%0], {%1,%2,%3,%4};"
                                 :: "r"(spill + (uint32_t)((mf*4 + kb) * 16)),
                                    "r"(alv.x), "r"(alv.y), "r"(alv.z), "r"(alv.w)
                                 : "memory");
                }
        }

        // ---- GEMM2: K=64; passes 0,1 use AH (regs) ----
        #pragma unroll
        for (int mf = 0; mf < 2; mf++)
            #pragma unroll
            for (int nf = 0; nf < 8; nf++)
                #pragma unroll
                for (int q = 0; q < 4; q++) C[mf][nf][q] = 0.f;

        #pragma unroll
        for (int pass = 0; pass < 2; pass++) {
            const uint32_t Wb = (pass == 1) ? aW2L : aW2H;
            #pragma unroll
            for (int kb = 0; kb < 4; kb++) {
                #pragma unroll
                for (int np = 0; np < 4; np++) {
                    uint32_t bf[4];
                    ldsm4t(bf, Wb + (uint32_t)((kb*16 + (lane & 7) + 8*((lane >> 3) & 1)) * SW
                                               + (np*16 + (lane >> 4) * 8) * 2));
                    #pragma unroll
                    for (int mf = 0; mf < 2; mf++) {
                        mma16816(C[mf][2*np],     AH[mf][kb], bf[0], bf[1]);
                        mma16816(C[mf][2*np + 1], AH[mf][kb], bf[2], bf[3]);
                    }
                }
            }
        }

        // ---- pass 2: reload AL from scratch (AH dead -> regs reused) ----
        {
            const uint32_t spill = sb + OFF_SPILL + (uint32_t)(t * SSP);
            uint32_t ALr[2][4][4];
            #pragma unroll
            for (int mf = 0; mf < 2; mf++)
                #pragma unroll
                for (int kb = 0; kb < 4; kb++)
                    asm volatile("ld.shared.v4.b32 {%0,%1,%2,%3}, [%4];"
                                 : "=r"(ALr[mf][kb][0]), "=r"(ALr[mf][kb][1]),
                                   "=r"(ALr[mf][kb][2]), "=r"(ALr[mf][kb][3])
                                 : "r"(spill + (uint32_t)((mf*4 + kb) * 16)));
            #pragma unroll
            for (int kb = 0; kb < 4; kb++) {
                #pragma unroll
                for (int np = 0; np < 4; np++) {
                    uint32_t bf[4];
                    ldsm4t(bf, aW2H + (uint32_t)((kb*16 + (lane & 7) + 8*((lane >> 3) & 1)) * SW
                                                 + (np*16 + (lane >> 4) * 8) * 2));
                    #pragma unroll
                    for (int mf = 0; mf < 2; mf++) {
                        mma16816(C[mf][2*np],     ALr[mf][kb], bf[0], bf[1]);
                        mma16816(C[mf][2*np + 1], ALr[mf][kb], bf[2], bf[3]);
                    }
                }
            }
        }

        // ---- scatter straight from fragments (b2 read from smem) ----
        #pragma unroll
        for (int mf = 0; mf < 2; mf++) {
            const int rl = m0 + 16*mf + (lane >> 2);
            const int rh = rl + 8;
            const int nrl = sRow[rl], ncl = sCol[rl];
            const int nrh = sRow[rh], nch = sCol[rh];
            const float* xl = g_xt + (size_t)nrl * DD;
            const float* xh = g_xt + (size_t)nrh * DD;
            float* sl = g_s + (size_t)ncl * DD;
            float* sh = g_s + (size_t)nch * DD;
            const int cb = 2 * (lane & 3);
            #pragma unroll
            for (int nf = 0; nf < 8; nf++) {
                const int c0 = nf*8 + cb;
                float2 bv = *(const float2*)(sB2 + c0);
                float2 xv = *(const float2*)(xl + c0);
                red_add_v2(sl + c0, (C[mf][nf][0] + bv.x) * xv.x,
                                    (C[mf][nf][1] + bv.y) * xv.y);
                float2 xv2 = *(const float2*)(xh + c0);
                red_add_v2(sh + c0, (C[mf][nf][2] + bv.x) * xv2.x,
                                    (C[mf][nf][3] + bv.y) * xv2.y);
            }
        }
        __syncthreads();   // spill region overlays A1 across warp boundaries
    }
}

// ---------------- agg = s / max(cnt,1), in place ---------------------------
__global__ void agg_kernel() {
    int idx = blockIdx.x * 256 + threadIdx.x;
    if (idx >= NN * (DD / 4)) return;
    int node = idx >> 4;
    float inv = 1.0f / fmaxf(g_cnt[node], 1.0f);
    float4 v = ((float4*)g_s)[idx];
    v.x *= inv; v.y *= inv; v.z *= inv; v.w *= inv;
    ((float4*)g_s)[idx] = v;
}

// ---------------- batch-norm normalize -------------------------------------
__global__ void bn_kernel(float* __restrict__ outp,
                          const float* __restrict__ gamma,
                          const float* __restrict__ beta)
{
    int idx = blockIdx.x * 256 + threadIdx.x;
    if (idx >= NN * (DD / 4)) return;
    int jb = (idx & 15) * 4;
    float4 h = ((const float4*)g_h)[idx];
    float r[4] = {h.x, h.y, h.z, h.w};
    float rr[4];
    #pragma unroll
    for (int u = 0; u < 4; u++) {
        int j = jb + u;
        double mu  = g_sum[j]   * (1.0 / NN);
        double var = g_sumsq[j] * (1.0 / NN) - mu * mu;
        float  sc  = gamma[j] * rsqrtf(fmaxf((float)var, 0.f) + 1e-5f);
        rr[u] = (float)((double)r[u] - mu) * sc + beta[j];
    }
    ((float4*)outp)[idx] = make_float4(rr[0], rr[1], rr[2], rr[3]);
}

// ---------------- launch ----------------------------------------------------
extern "C" void kernel_launch(void* const* d_in, const int* in_sizes, int n_in,
                              void* d_out, int out_size)
{
    const float* x         = (const float*)d_in[0];
    const float* pos       = (const float*)d_in[1];
    const float* edge_attr = (const float*)d_in[2];
    const int*   row       = (const int*)  d_in[3];
    const int*   col       = (const int*)  d_in[4];
    const float* nW1 = (const float*)d_in[5];
    const float* nb1 = (const float*)d_in[6];
    const float* nW2 = (const float*)d_in[7];
    const float* nb2 = (const float*)d_in[8];
    const float* eW1 = (const float*)d_in[9];
    const float* eb1 = (const float*)d_in[10];
    const float* eW2 = (const float*)d_in[11];
    const float* eb2 = (const float*)d_in[12];
    const float* oW1 = (const float*)d_in[13];
    const float* ob1 = (const float*)d_in[14];
    const float* oW2 = (const float*)d_in[15];
    const float* ob2 = (const float*)d_in[16];
    const float* gam = (const float*)d_in[17];
    const float* bet = (const float*)d_in[18];
    float* outp = (float*)d_out;

    cudaFuncSetAttribute(edge_kernel,
                         cudaFuncAttributeMaxDynamicSharedMemorySize, EDGE_SMEM);

    zero_kernel<<<512, 256>>>();                                   // launch 1
    mlp_kernel<false><<<(NN + 127) / 128, 128>>>(x, nW1, nb1, nW2, nb2);  // 2
    dummy_kernel<<<1, 32>>>();                                     // 3 (shim)
    edge_kernel<<<592, 128, EDGE_SMEM>>>(pos, edge_attr, row, col,
                                         eW1, eb1, eW2, eb2);      // 4 <- profiled
    agg_kernel<<<(NN * (DD / 4) + 255) / 256, 256>>>();            // 5
    mlp_kernel<true><<<(NN + 127) / 128, 128>>>(x, oW1, ob1, oW2, ob2);   // 6
    bn_kernel<<<(NN * (DD / 4) + 255) / 256, 256>>>(outp, gam, bet);      // 7
}

// round 15
// speedup vs baseline: 1.5890x; 1.0150x over previous
#include <cuda_runtime.h>
#include <cuda_bf16.h>
#include <math.h>
#include <stdint.h>

#define NN 100000
#define EE 1600000
#define DD 64
#define EDIM 16
#define SHC 9
#define FEAT 25
#define TE 128            // edges per tile
#define NT (EE / TE)      // 12500

typedef unsigned long long u64;

// ---------------- scratch (device globals) ----------------------------------
__device__ float  g_xt[(size_t)NN * DD];
__device__ float  g_s [(size_t)NN * DD];
__device__ float  g_cnt[NN];
__device__ float  g_h [(size_t)NN * DD];
__device__ double g_sum[DD];
__device__ double g_sumsq[DD];

__device__ __forceinline__ float silu_f(float a) {
    return a / (1.0f + __expf(-a));
}
__device__ __forceinline__ u64 pk2(float x, float y) {
    u64 r; asm("mov.b64 %0, {%1,%2};" : "=l"(r) : "f"(x), "f"(y)); return r;
}
__device__ __forceinline__ void upk2(u64 v, float& x, float& y) {
    asm("mov.b64 {%0,%1}, %2;" : "=f"(x), "=f"(y) : "l"(v));
}
__device__ __forceinline__ void fma2(u64& d, u64 a, u64 b) {
    asm("fma.rn.f32x2 %0, %1, %2, %0;" : "+l"(d) : "l"(a), "l"(b));
}
__device__ __forceinline__ void red_add_v2(float* p, float a, float b) {
    asm volatile("red.global.add.v2.f32 [%0], {%1,%2};"
                 :: "l"(p), "f"(a), "f"(b) : "memory");
}
__device__ __forceinline__ uint32_t s2u(const void* p) {
    uint32_t a;
    asm("{ .reg .u64 t; cvta.to.shared.u64 t, %1; cvt.u32.u64 %0, t; }" : "=r"(a) : "l"(p));
    return a;
}

// ---------------- mma.sync / ldmatrix primitives -----------------------------
__device__ __forceinline__ void ldsm4(uint32_t* r, uint32_t a) {
    asm volatile("ldmatrix.sync.aligned.m8n8.x4.shared.b16 {%0,%1,%2,%3}, [%4];"
                 : "=r"(r[0]), "=r"(r[1]), "=r"(r[2]), "=r"(r[3]) : "r"(a));
}
__device__ __forceinline__ void ldsm4t(uint32_t* r, uint32_t a) {
    asm volatile("ldmatrix.sync.aligned.m8n8.x4.trans.shared.b16 {%0,%1,%2,%3}, [%4];"
                 : "=r"(r[0]), "=r"(r[1]), "=r"(r[2]), "=r"(r[3]) : "r"(a));
}
__device__ __forceinline__ void mma16816(float* c, const uint32_t* a,
                                         uint32_t b0, uint32_t b1) {
    asm volatile(
        "mma.sync.aligned.m16n8k16.row.col.f32.bf16.bf16.f32 "
        "{%0,%1,%2,%3}, {%4,%5,%6,%7}, {%8,%9}, {%0,%1,%2,%3};"
        : "+f"(c[0]), "+f"(c[1]), "+f"(c[2]), "+f"(c[3])
        : "r"(a[0]), "r"(a[1]), "r"(a[2]), "r"(a[3]), "r"(b0), "r"(b1));
}

__device__ __forceinline__ void split8(const float* v, uint4& hi, uint4& lo) {
    uint32_t h[4], l[4];
    #pragma unroll
    for (int p = 0; p < 4; p++) {
        float a = v[2*p], b = v[2*p+1];
        __nv_bfloat162 hh = __floats2bfloat162_rn(a, b);
        float la = a - __bfloat162float(__low2bfloat16(hh));
        float lb = b - __bfloat162float(__high2bfloat16(hh));
        __nv_bfloat162 ll = __floats2bfloat162_rn(la, lb);
        h[p] = *(uint32_t*)&hh; l[p] = *(uint32_t*)&ll;
    }
    hi = make_uint4(h[0], h[1], h[2], h[3]);
    lo = make_uint4(l[0], l[1], l[2], l[3]);
}
__device__ __forceinline__ void split2(float a, float b, uint32_t& hi, uint32_t& lo) {
    __nv_bfloat162 hh = __floats2bfloat162_rn(a, b);
    float la = a - __bfloat162float(__low2bfloat16(hh));
    float lb = b - __bfloat162float(__high2bfloat16(hh));
    __nv_bfloat162 ll = __floats2bfloat162_rn(la, lb);
    hi = *(uint32_t*)&hh; lo = *(uint32_t*)&ll;
}

// ---------------- zero scratch + dummy (ncu launch-slot shim) ----------------
__global__ void zero_kernel() {
    int idx = blockIdx.x * blockDim.x + threadIdx.x;
    int stride = gridDim.x * blockDim.x;
    float4 z = make_float4(0.f, 0.f, 0.f, 0.f);
    for (int i = idx; i < NN * (DD / 4); i += stride)
        ((float4*)g_s)[i] = z;
    for (int i = idx; i < NN; i += stride)
        g_cnt[i] = 0.f;
    if (idx < DD) { g_sum[idx] = 0.0; g_sumsq[idx] = 0.0; }
}
__global__ void dummy_kernel() {}   // keeps edge_kernel in the profiled slot

// ---------------- node / output MLP (R5, unchanged) --------------------------
template <bool IS_OUT>
__global__ __launch_bounds__(128)
void mlp_kernel(const float* __restrict__ x,
                const float* __restrict__ W1, const float* __restrict__ b1,
                const float* __restrict__ W2, const float* __restrict__ b2)
{
    constexpr int IND = IS_OUT ? 128 : 64;
    __shared__ __align__(16) float sW1[IND * DD];
    __shared__ __align__(16) float sW2[DD * DD];
    const int t = threadIdx.x;
    for (int i = t; i < IND * DD; i += 128) sW1[i] = W1[i];
    for (int i = t; i < DD * DD;  i += 128) sW2[i] = W2[i];
    __syncthreads();

    const int id = blockIdx.x * 128 + t;
    const bool valid = (id < NN);
    const int rid = valid ? id : (NN - 1);

    const float4* rowA;
    const float4* rowB = nullptr;
    if (IS_OUT) {
        rowA = (const float4*)(g_s + (size_t)rid * DD);
        rowB = (const float4*)(x   + (size_t)rid * DD);
    } else {
        rowA = (const float4*)(x + (size_t)rid * DD);
    }

    u64 outp[32];
    {
        const ulonglong2* b2v = (const ulonglong2*)b2;
        #pragma unroll
        for (int q = 0; q < 16; q++) { ulonglong2 bv = b2v[q]; outp[2*q] = bv.x; outp[2*q+1] = bv.y; }
    }

    #pragma unroll 1
    for (int ch = 0; ch < 4; ch++) {
        const int base = ch * 16;
        u64 hp[8];
        {
            const ulonglong2* b1v = (const ulonglong2*)(b1 + base);
            #pragma unroll
            for (int q = 0; q < 4; q++) { ulonglong2 bv = b1v[q]; hp[2*q] = bv.x; hp[2*q+1] = bv.y; }
        }
        #pragma unroll 2
        for (int g = 0; g < IND / 4; g++) {
            float4 v;
            if (IS_OUT) v = (g < 16) ? rowA[g] : rowB[g - 16];
            else        v = rowA[g];
            const float fv[4] = {v.x, v.y, v.z, v.w};
            #pragma unroll
            for (int u = 0; u < 4; u++) {
                const u64 fmp = pk2(fv[u], fv[u]);
                const ulonglong2* wr = (const ulonglong2*)(sW1 + (g*4 + u) * DD + base);
                #pragma unroll
                for (int q = 0; q < 4; q++) {
                    ulonglong2 w = wr[q];
                    fma2(hp[2*q], fmp, w.x);
                    fma2(hp[2*q+1], fmp, w.y);
                }
            }
        }
        float h16[16];
        #pragma unroll
        for (int i = 0; i < 8; i++) {
            float a, b; upk2(hp[i], a, b);
            h16[2*i] = silu_f(a); h16[2*i+1] = silu_f(b);
        }
        #pragma unroll
        for (int kk = 0; kk < 16; kk++) {
            const u64 hvp = pk2(h16[kk], h16[kk]);
            const ulonglong2* wr = (const ulonglong2*)(sW2 + (base + kk) * DD);
            #pragma unroll
            for (int q = 0; q < 16; q++) {
                ulonglong2 w = wr[q];
                fma2(outp[2*q], hvp, w.x);
                fma2(outp[2*q+1], hvp, w.y);
            }
        }
    }

    float* dst = IS_OUT ? g_h : g_xt;
    if (valid) {
        ulonglong2* o = (ulonglong2*)(dst + (size_t)id * DD);
        #pragma unroll
        for (int q = 0; q < 16; q++) {
            ulonglong2 w; w.x = outp[2*q]; w.y = outp[2*q+1];
            o[q] = w;
        }
    }

    if (IS_OUT) {
        #pragma unroll
        for (int jp = 0; jp < 32; jp++) {
            float va, vb; upk2(outp[jp], va, vb);
            if (!valid) { va = 0.f; vb = 0.f; }
            float s0 = va, q0 = va * va, s1 = vb, q1 = vb * vb;
            #pragma unroll
            for (int o = 16; o; o >>= 1) {
                s0 += __shfl_down_sync(0xffffffffu, s0, o);
                q0 += __shfl_down_sync(0xffffffffu, q0, o);
                s1 += __shfl_down_sync(0xffffffffu, s1, o);
                q1 += __shfl_down_sync(0xffffffffu, q1, o);
            }
            if ((t & 31) == 0) {
                atomicAdd(&g_sum[2*jp],     (double)s0);
                atomicAdd(&g_sumsq[2*jp],   (double)q0);
                atomicAdd(&g_sum[2*jp+1],   (double)s1);
                atomicAdd(&g_sumsq[2*jp+1], (double)q1);
            }
        }
    }
}

// ---------------- fused edge kernel: N-split GEMM2, no spill, warp-private ---
// R14 + : GEMM2 processes N in two 32-col halves (C2 = 32 regs) so AH and AL
// both stay in registers -> no smem spill, no block barriers in the tile loop
// (A1/sRow/sCol rows are warp-private again). row/col for the next tile are
// prefetched before the scatter to break the phase-1 LDG->LDG chain.
#define SA1 80
#define SW  144
#define OFF_B2   0
#define OFF_ROW  256
#define OFF_COL  768
#define OFF_A1H  1280
#define OFF_A1L  11520
#define OFF_W1H  21760
#define OFF_W1L  26368
#define OFF_W2H  30976
#define OFF_W2L  40192
#define EDGE_SMEM 49408

__global__ __launch_bounds__(128, 4)
void edge_kernel(const float* __restrict__ pos,
                 const float* __restrict__ edge_attr,
                 const int*   __restrict__ row,
                 const int*   __restrict__ col,
                 const float* __restrict__ W1, const float* __restrict__ b1,
                 const float* __restrict__ W2, const float* __restrict__ b2)
{
    extern __shared__ __align__(16) char smem[];
    const uint32_t sb = s2u(smem);
    const int t    = threadIdx.x;
    const int wid  = t >> 5;
    const int lane = t & 31;
    const int m0   = wid * 32;

    float* sB2  = (float*)(smem + OFF_B2);
    int*   sRow = (int*)(smem + OFF_ROW);
    int*   sCol = (int*)(smem + OFF_COL);

    // ---- one-time: weights -> bf16 hi/lo, [k][n] row-major, stride SW ----
    for (int i = t; i < 32 * 64; i += 128) {
        int k = i >> 6, n = i & 63;
        float v = (k < FEAT) ? W1[k * 64 + n] : ((k == FEAT) ? b1[n] : 0.f);
        uint32_t o = (uint32_t)(k * SW + n * 2);
        __nv_bfloat16 h = __float2bfloat16(v);
        *(__nv_bfloat16*)(smem + OFF_W1H + o) = h;
        *(__nv_bfloat16*)(smem + OFF_W1L + o) = __float2bfloat16(v - __bfloat162float(h));
    }
    for (int i = t; i < 64 * 64; i += 128) {
        int k = i >> 6, n = i & 63;
        float v = W2[k * 64 + n];
        uint32_t o = (uint32_t)(k * SW + n * 2);
        __nv_bfloat16 h = __float2bfloat16(v);
        *(__nv_bfloat16*)(smem + OFF_W2H + o) = h;
        *(__nv_bfloat16*)(smem + OFF_W2L + o) = __float2bfloat16(v - __bfloat162float(h));
    }
    if (t < 64) sB2[t] = b2[t];
    __syncthreads();

    const uint32_t aA1H = sb + OFF_A1H, aA1L = sb + OFF_A1L;
    const uint32_t aW1H = sb + OFF_W1H, aW1L = sb + OFF_W1L;
    const uint32_t aW2H = sb + OFF_W2H, aW2L = sb + OFF_W2L;

    // prefetched indices for the first tile
    int pr_r = row[blockIdx.x * TE + t];
    int pr_c = col[blockIdx.x * TE + t];

    for (int tile = blockIdx.x; tile < NT; tile += gridDim.x) {
        const int e = tile * TE + t;

        // ---- phase 1: per-edge features (bf16 hi/lo) -> A1 row t ----
        {
            const int r = pr_r;
            const int c = pr_c;
            sRow[t] = r; sCol[t] = c;

            float px = pos[3*r]   - pos[3*c];
            float py = pos[3*r+1] - pos[3*c+1];
            float pz = pos[3*r+2] - pos[3*c+2];
            float len = sqrtf(px*px + py*py + pz*pz + 1e-12f);
            float dx = px / len, dy = py / len, dz = pz / len;
            float n2 = sqrtf(dx*dx + dy*dy + dz*dz) + 1e-10f;
            dx /= n2; dy /= n2; dz /= n2;

            float f[32];
            f[0] = 0.28209479177387814f;
            f[1] = 0.4886025119029199f * dy;
            f[2] = 0.4886025119029199f * dz;
            f[3] = 0.4886025119029199f * dx;
            f[4] = 1.0925484305920792f * dx * dy;
            f[5] = 1.0925484305920792f * dy * dz;
            f[6] = 0.31539156525252005f * (3.0f * dz * dz - 1.0f);
            f[7] = 1.0925484305920792f * dx * dz;
            f[8] = 0.5462742152960396f * (dx*dx - dy*dy);
            const float4* ea = (const float4*)(edge_attr + (size_t)e * EDIM);
            #pragma unroll
            for (int i = 0; i < 4; i++) {
                float4 v = ea[i];
                f[SHC + 4*i]   = v.x; f[SHC + 4*i+1] = v.y;
                f[SHC + 4*i+2] = v.z; f[SHC + 4*i+3] = v.w;
            }
            f[25] = 1.0f;
            #pragma unroll
            for (int k = 26; k < 32; k++) f[k] = 0.f;

            #pragma unroll
            for (int cc = 0; cc < 4; cc++) {
                uint4 hi, lo;
                split8(f + cc*8, hi, lo);
                *(uint4*)(smem + OFF_A1H + t*SA1 + cc*16) = hi;
                *(uint4*)(smem + OFF_A1L + t*SA1 + cc*16) = lo;
            }
            atomicAdd(&g_cnt[c], 1.0f);
        }
        __syncwarp();    // A1/sRow/sCol rows are warp-private

        // ---- GEMM1: K=32, 3 passes, C1 in f32 ----
        float C1[2][8][4];
        #pragma unroll
        for (int mf = 0; mf < 2; mf++)
            #pragma unroll
            for (int nf = 0; nf < 8; nf++)
                #pragma unroll
                for (int q = 0; q < 4; q++) C1[mf][nf][q] = 0.f;

        #pragma unroll
        for (int pass = 0; pass < 3; pass++) {
            const uint32_t Ab = (pass == 2) ? aA1L : aA1H;
            const uint32_t Wb = (pass == 1) ? aW1L : aW1H;
            #pragma unroll
            for (int ks = 0; ks < 2; ks++) {
                uint32_t af[2][4];
                #pragma unroll
                for (int mf = 0; mf < 2; mf++)
                    ldsm4(af[mf], Ab + (uint32_t)((m0 + 16*mf + (lane & 15)) * SA1
                                                  + ks*32 + (lane >> 4) * 16));
                #pragma unroll
                for (int np = 0; np < 4; np++) {
                    uint32_t bf[4];
                    ldsm4t(bf, Wb + (uint32_t)((ks*16 + (lane & 7) + 8*((lane >> 3) & 1)) * SW
                                               + (np*16 + (lane >> 4) * 8) * 2));
                    #pragma unroll
                    for (int mf = 0; mf < 2; mf++) {
                        mma16816(C1[mf][2*np],     af[mf], bf[0], bf[1]);
                        mma16816(C1[mf][2*np + 1], af[mf], bf[2], bf[3]);
                    }
                }
            }
        }
        __syncwarp();

        // ---- silu + pack C1 -> A2 fragments, hi AND lo in registers ----
        uint32_t AH[2][4][4], AL[2][4][4];
        #pragma unroll
        for (int mf = 0; mf < 2; mf++)
            #pragma unroll
            for (int kb = 0; kb < 4; kb++) {
                float s00 = silu_f(C1[mf][2*kb][0]),   s01 = silu_f(C1[mf][2*kb][1]);
                float s02 = silu_f(C1[mf][2*kb][2]),   s03 = silu_f(C1[mf][2*kb][3]);
                float s10 = silu_f(C1[mf][2*kb+1][0]), s11 = silu_f(C1[mf][2*kb+1][1]);
                float s12 = silu_f(C1[mf][2*kb+1][2]), s13 = silu_f(C1[mf][2*kb+1][3]);
                split2(s00, s01, AH[mf][kb][0], AL[mf][kb][0]);
                split2(s02, s03, AH[mf][kb][1], AL[mf][kb][1]);
                split2(s10, s11, AH[mf][kb][2], AL[mf][kb][2]);
                split2(s12, s13, AH[mf][kb][3], AL[mf][kb][3]);
            }

        // ---- prefetch next tile's row/col (hide the idx->pos LDG chain) ----
        {
            const int nxt = tile + gridDim.x;
            if (nxt < NT) {
                const int e2 = nxt * TE + t;
                pr_r = row[e2];
                pr_c = col[e2];
            }
        }

        // ---- GEMM2 in two N-halves (C2 = 32 regs), scatter each half ----
        #pragma unroll
        for (int nh = 0; nh < 2; nh++) {
            float C2[2][4][4];
            #pragma unroll
            for (int mf = 0; mf < 2; mf++)
                #pragma unroll
                for (int nfl = 0; nfl < 4; nfl++)
                    #pragma unroll
                    for (int q = 0; q < 4; q++) C2[mf][nfl][q] = 0.f;

            #pragma unroll
            for (int pass = 0; pass < 3; pass++) {
                const uint32_t Wb = (pass == 1) ? aW2L : aW2H;
                const bool useLo = (pass == 2);
                #pragma unroll
                for (int kb = 0; kb < 4; kb++) {
                    #pragma unroll
                    for (int npl = 0; npl < 2; npl++) {
                        const int np = nh*2 + npl;
                        uint32_t bf[4];
                        ldsm4t(bf, Wb + (uint32_t)((kb*16 + (lane & 7) + 8*((lane >> 3) & 1)) * SW
                                                   + (np*16 + (lane >> 4) * 8) * 2));
                        #pragma unroll
                        for (int mf = 0; mf < 2; mf++) {
                            const uint32_t* af = useLo ? AL[mf][kb] : AH[mf][kb];
                            mma16816(C2[mf][2*npl],     af, bf[0], bf[1]);
                            mma16816(C2[mf][2*npl + 1], af, bf[2], bf[3]);
                        }
                    }
                }
            }

            // scatter this N-half straight from fragments
            #pragma unroll
            for (int mf = 0; mf < 2; mf++) {
                const int rl = m0 + 16*mf + (lane >> 2);
                const int rh = rl + 8;
                const int nrl = sRow[rl], ncl = sCol[rl];
                const int nrh = sRow[rh], nch = sCol[rh];
                const float* xl = g_xt + (size_t)nrl * DD;
                const float* xh = g_xt + (size_t)nrh * DD;
                float* sl = g_s + (size_t)ncl * DD;
                float* sh = g_s + (size_t)nch * DD;
                const int cb = 2 * (lane & 3);
                #pragma unroll
                for (int nfl = 0; nfl < 4; nfl++) {
                    const int c0 = (nh*4 + nfl)*8 + cb;
                    float2 bv = *(const float2*)(sB2 + c0);
                    float2 xv = *(const float2*)(xl + c0);
                    red_add_v2(sl + c0, (C2[mf][nfl][0] + bv.x) * xv.x,
                                        (C2[mf][nfl][1] + bv.y) * xv.y);
                    float2 xv2 = *(const float2*)(xh + c0);
                    red_add_v2(sh + c0, (C2[mf][nfl][2] + bv.x) * xv2.x,
                                        (C2[mf][nfl][3] + bv.y) * xv2.y);
                }
            }
        }
        __syncwarp();   // protect A1/sRow/sCol (warp-private) before next tile
    }
}

// ---------------- agg = s / max(cnt,1), in place ---------------------------
__global__ void agg_kernel() {
    int idx = blockIdx.x * 256 + threadIdx.x;
    if (idx >= NN * (DD / 4)) return;
    int node = idx >> 4;
    float inv = 1.0f / fmaxf(g_cnt[node], 1.0f);
    float4 v = ((float4*)g_s)[idx];
    v.x *= inv; v.y *= inv; v.z *= inv; v.w *= inv;
    ((float4*)g_s)[idx] = v;
}

// ---------------- batch-norm normalize -------------------------------------
__global__ void bn_kernel(float* __restrict__ outp,
                          const float* __restrict__ gamma,
                          const float* __restrict__ beta)
{
    int idx = blockIdx.x * 256 + threadIdx.x;
    if (idx >= NN * (DD / 4)) return;
    int jb = (idx & 15) * 4;
    float4 h = ((const float4*)g_h)[idx];
    float r[4] = {h.x, h.y, h.z, h.w};
    float rr[4];
    #pragma unroll
    for (int u = 0; u < 4; u++) {
        int j = jb + u;
        double mu  = g_sum[j]   * (1.0 / NN);
        double var = g_sumsq[j] * (1.0 / NN) - mu * mu;
        float  sc  = gamma[j] * rsqrtf(fmaxf((float)var, 0.f) + 1e-5f);
        rr[u] = (float)((double)r[u] - mu) * sc + beta[j];
    }
    ((float4*)outp)[idx] = make_float4(rr[0], rr[1], rr[2], rr[3]);
}

// ---------------- launch ----------------------------------------------------
extern "C" void kernel_launch(void* const* d_in, const int* in_sizes, int n_in,
                              void* d_out, int out_size)
{
    const float* x         = (const float*)d_in[0];
    const float* pos       = (const float*)d_in[1];
    const float* edge_attr = (const float*)d_in[2];
    const int*   row       = (const int*)  d_in[3];
    const int*   col       = (const int*)  d_in[4];
    const float* nW1 = (const float*)d_in[5];
    const float* nb1 = (const float*)d_in[6];
    const float* nW2 = (const float*)d_in[7];
    const float* nb2 = (const float*)d_in[8];
    const float* eW1 = (const float*)d_in[9];
    const float* eb1 = (const float*)d_in[10];
    const float* eW2 = (const float*)d_in[11];
    const float* eb2 = (const float*)d_in[12];
    const float* oW1 = (const float*)d_in[13];
    const float* ob1 = (const float*)d_in[14];
    const float* oW2 = (const float*)d_in[15];
    const float* ob2 = (const float*)d_in[16];
    const float* gam = (const float*)d_in[17];
    const float* bet = (const float*)d_in[18];
    float* outp = (float*)d_out;

    cudaFuncSetAttribute(edge_kernel,
                         cudaFuncAttributeMaxDynamicSharedMemorySize, EDGE_SMEM);

    zero_kernel<<<512, 256>>>();                                   // launch 1
    mlp_kernel<false><<<(NN + 127) / 128, 128>>>(x, nW1, nb1, nW2, nb2);  // 2
    dummy_kernel<<<1, 32>>>();                                     // 3 (shim)
    edge_kernel<<<592, 128, EDGE_SMEM>>>(pos, edge_attr, row, col,
                                         eW1, eb1, eW2, eb2);      // 4 <- profiled
    agg_kernel<<<(NN * (DD / 4) + 255) / 256, 256>>>();            // 5
    mlp_kernel<true><<<(NN + 127) / 128, 128>>>(x, oW1, ob1, oW2, ob2);   // 6
    bn_kernel<<<(NN * (DD / 4) + 255) / 256, 256>>>(outp, gam, bet);      // 7
}